// round 9
// baseline (speedup 1.0000x reference)
#include <cuda_runtime.h>

#define BB 2
#define CC 128
#define HHW 56
#define NN 3136
#define HEADS 4
#define HD 32
#define AG 49
#define SCALE 0.1767766952966369f  // 32^-0.5
#define LN_EPS 1e-5f
#define KSPLIT 14
#define NTILES 49          // NN / 64

#define KP 36  // K/Q smem row pad (floats) -> conflict-free mma B/A loads
#define VP 40  // V smem row pad
#define PP 68  // P smem row pad

// ---------------- scratch (device globals; no allocation allowed) ----------------
__device__ float g_q[BB * HEADS * NN * HD];
__device__ float g_k[BB * HEADS * NN * HD];   // stored tf32-rounded
__device__ float g_v[BB * HEADS * NN * HD];   // stored tf32-rounded
__device__ float g_agent[BB * HEADS * AG * HD];
__device__ float g_qc[BB * HEADS * NN * HD];  // stored tf32-rounded, pre-scaled
__device__ float g_ctx[BB * NN * CC];
// split-K partials (no max needed: logits are tiny, exp(s) directly)
__device__ float g_po[KSPLIT * BB * HEADS * NN * HD];
__device__ float g_pl[KSPLIT * BB * HEADS * NN];

// ---------------- tf32 helpers ----------------
__device__ __forceinline__ float tf32r(float x) {
    asm("cvt.rna.tf32.f32 %0, %0;" : "+f"(x));
    return x;
}

__device__ __forceinline__ void mma8(float& c0, float& c1, float& c2, float& c3,
                                     unsigned a0, unsigned a1, unsigned a2, unsigned a3,
                                     unsigned b0, unsigned b1) {
    asm("mma.sync.aligned.m16n8k8.row.col.f32.tf32.tf32.f32 "
        "{%0,%1,%2,%3}, {%4,%5,%6,%7}, {%8,%9}, {%0,%1,%2,%3};"
        : "+f"(c0), "+f"(c1), "+f"(c2), "+f"(c3)
        : "r"(a0), "r"(a1), "r"(a2), "r"(a3), "r"(b0), "r"(b1));
}

// =====================================================================
// Kernel 1: QKV 1x1 conv == GEMM  Y[b,o,n] = sum_c W[o,c] * X[b,c,n]
// K and V outputs are tf32-rounded at the source (consumed only by mma).
// =====================================================================
__global__ __launch_bounds__(256) void qkv_kernel(const float* __restrict__ x,
                                                  const float* __restrict__ w) {
    __shared__ float Wsh[32][68];
    __shared__ float Xsh[32][68];

    const int b = blockIdx.z;
    const int o0 = blockIdx.y * 64;
    const int n0 = blockIdx.x * 64;
    const int t = threadIdx.x;
    const int tr = t >> 4;
    const int tc = t & 15;

    float acc[4][4];
#pragma unroll
    for (int i = 0; i < 4; i++)
#pragma unroll
        for (int j = 0; j < 4; j++) acc[i][j] = 0.f;

    const float* xb = x + (size_t)b * CC * NN;

    for (int k0 = 0; k0 < CC; k0 += 32) {
        {
            int wo = t >> 2, wc = (t & 3) * 8;
            float4 wa = *(const float4*)&w[(o0 + wo) * CC + k0 + wc];
            float4 wb = *(const float4*)&w[(o0 + wo) * CC + k0 + wc + 4];
            Wsh[wc + 0][wo] = wa.x; Wsh[wc + 1][wo] = wa.y;
            Wsh[wc + 2][wo] = wa.z; Wsh[wc + 3][wo] = wa.w;
            Wsh[wc + 4][wo] = wb.x; Wsh[wc + 5][wo] = wb.y;
            Wsh[wc + 6][wo] = wb.z; Wsh[wc + 7][wo] = wb.w;
        }
        {
            int xc = t >> 3, xn = (t & 7) * 8;
            float4 xa = *(const float4*)&xb[(size_t)(k0 + xc) * NN + n0 + xn];
            float4 xv = *(const float4*)&xb[(size_t)(k0 + xc) * NN + n0 + xn + 4];
            *(float4*)&Xsh[xc][xn] = xa;
            *(float4*)&Xsh[xc][xn + 4] = xv;
        }
        __syncthreads();
#pragma unroll
        for (int kk = 0; kk < 32; kk++) {
            float4 a4 = *(const float4*)&Wsh[kk][tr * 4];
            float4 b4 = *(const float4*)&Xsh[kk][tc * 4];
            float a[4] = {a4.x, a4.y, a4.z, a4.w};
            float bb[4] = {b4.x, b4.y, b4.z, b4.w};
#pragma unroll
            for (int i = 0; i < 4; i++)
#pragma unroll
                for (int j = 0; j < 4; j++) acc[i][j] += a[i] * bb[j];
        }
        __syncthreads();
    }

    const int obase = o0 + tr * 4;
    const int part = obase >> 7;
    const int h = (obase >> 5) & 3;
    const int d0 = obase & 31;
    float* dst = (part == 0) ? g_q : (part == 1) ? g_k : g_v;
    dst += (size_t)(b * HEADS + h) * NN * HD;
#pragma unroll
    for (int j = 0; j < 4; j++) {
        int n = n0 + tc * 4 + j;
        float4 v4 = make_float4(acc[0][j], acc[1][j], acc[2][j], acc[3][j]);
        if (part != 0) {
            v4.x = tf32r(v4.x); v4.y = tf32r(v4.y);
            v4.z = tf32r(v4.z); v4.w = tf32r(v4.w);
        }
        *(float4*)&dst[(size_t)n * HD + d0] = v4;
    }
}

// =====================================================================
// Kernel 2: agent pooling — exact 8x8 block mean
// =====================================================================
__global__ void pool_kernel(const float* __restrict__ x) {
    int idx = blockIdx.x * 256 + threadIdx.x;
    if (idx >= BB * CC * AG) return;
    int a = idx % AG;
    int c = (idx / AG) % CC;
    int b = idx / (AG * CC);
    int ai = a / 7, aj = a % 7;
    const float* p = x + ((size_t)(b * CC + c) * HHW + ai * 8) * HHW + aj * 8;
    float s = 0.f;
#pragma unroll
    for (int r = 0; r < 8; r++) {
        float4 u = *(const float4*)&p[r * HHW];
        float4 u2 = *(const float4*)&p[r * HHW + 4];
        s += u.x + u.y + u.z + u.w + u2.x + u2.y + u2.z + u2.w;
    }
    s *= (1.0f / 64.0f);
    g_agent[((size_t)(b * HEADS + c / HD) * AG + a) * HD + (c % HD)] = s;
}

// =====================================================================
// Kernel 3: stage 1 — softmax over 49 agent tokens; output tf32-rounded
// and pre-scaled by SCALE (stage-2 logits).
// =====================================================================
__global__ __launch_bounds__(256) void stage1_kernel() {
    __shared__ float Ash[AG][HD];
    const int bh = blockIdx.y;
    const int n = blockIdx.x * 256 + threadIdx.x;

    {
        const float4* src = (const float4*)(g_agent + (size_t)bh * AG * HD);
        float4* dstp = (float4*)&Ash[0][0];
        for (int i = threadIdx.x; i < AG * HD / 4; i += 256) dstp[i] = src[i];
    }
    __syncthreads();
    if (n >= NN) return;

    float4 q[8];
    const float4* qp = (const float4*)(g_q + ((size_t)bh * NN + n) * HD);
#pragma unroll
    for (int i = 0; i < 8; i++) q[i] = qp[i];

    float l = 0.f;
    float4 qc[8];
#pragma unroll
    for (int i = 0; i < 8; i++) qc[i] = make_float4(0.f, 0.f, 0.f, 0.f);

#pragma unroll 7
    for (int a = 0; a < AG; a++) {
        const float4* ar = (const float4*)&Ash[a][0];
        float s = 0.f;
#pragma unroll
        for (int i = 0; i < 8; i++) {
            float4 av = ar[i];
            s += q[i].x * av.x + q[i].y * av.y + q[i].z * av.z + q[i].w * av.w;
        }
        float p = __expf(s * SCALE);  // logits tiny; no max needed
        l += p;
#pragma unroll
        for (int i = 0; i < 8; i++) {
            float4 av = ar[i];
            qc[i].x += p * av.x; qc[i].y += p * av.y;
            qc[i].z += p * av.z; qc[i].w += p * av.w;
        }
    }
    float inv = SCALE / l;
    float4* op = (float4*)(g_qc + ((size_t)bh * NN + n) * HD);
#pragma unroll
    for (int i = 0; i < 8; i++) {
        float4 v = qc[i];
        op[i] = make_float4(tf32r(v.x * inv), tf32r(v.y * inv),
                            tf32r(v.z * inv), tf32r(v.w * inv));
    }
}

// =====================================================================
// Kernel 4: stage 2 — tf32 mma flash attention, M=32 per warp.
// 64 threads = 2 warps; each warp owns 32 query rows (two m16 blocks
// that SHARE every K/V B-fragment load -> per-row LDS traffic 0.64x R7).
// Split-K = 14 (3 or 4 key tiles per split; partials are plain sums).
// Qsh overlays Psh (Q only read in prologue, fenced by staging sync).
// =====================================================================
__global__ __launch_bounds__(64) void flash_kernel() {
    __shared__ float Ksh[64][KP];
    __shared__ float Vsh[64][VP];
    __shared__ float Psh[2][32][PP];
    float (*Qsh)[KP] = (float(*)[KP])&Psh[0][0][0];  // 64x36 fits in 2x32x68

    const int bh = blockIdx.y;
    const int z = blockIdx.z;
    const int t = threadIdx.x;
    const int w = t >> 5;        // 0..1
    const int lane = t & 31;
    const int lr = lane >> 2;    // 0..7
    const int lc = lane & 3;     // 0..3
    const int nq0 = blockIdx.x * 64;

    // stage Q tile (64 x 32), coalesced
    {
        const float4* src = (const float4*)(g_qc + ((size_t)bh * NN + nq0) * HD);
#pragma unroll
        for (int i = t; i < 512; i += 64) {
            int r = i >> 3, c = i & 7;
            *(float4*)&Qsh[r][c * 4] = src[i];
        }
    }
    __syncthreads();

    // Q A-fragments: [mb][kc][reg]; warp rows w*32 + mb*16 + {lr, lr+8}
    unsigned qa[2][4][4];
#pragma unroll
    for (int mb = 0; mb < 2; mb++) {
        const int r0 = w * 32 + mb * 16;
#pragma unroll
        for (int kc = 0; kc < 4; kc++) {
            qa[mb][kc][0] = __float_as_uint(Qsh[r0 + lr][kc * 8 + lc]);
            qa[mb][kc][1] = __float_as_uint(Qsh[r0 + lr + 8][kc * 8 + lc]);
            qa[mb][kc][2] = __float_as_uint(Qsh[r0 + lr][kc * 8 + lc + 4]);
            qa[mb][kc][3] = __float_as_uint(Qsh[r0 + lr + 8][kc * 8 + lc + 4]);
        }
    }
    __syncthreads();  // Q reads done before Psh overlay is written

    float o[2][4][4];
#pragma unroll
    for (int mb = 0; mb < 2; mb++)
#pragma unroll
        for (int dc = 0; dc < 4; dc++)
#pragma unroll
            for (int i = 0; i < 4; i++) o[mb][dc][i] = 0.f;
    float la[2] = {0.f, 0.f}, lb[2] = {0.f, 0.f};

    const float* kbase = g_k + (size_t)bh * NN * HD;
    const float* vbase = g_v + (size_t)bh * NN * HD;

    const int tstart = (NTILES * z) / KSPLIT;
    const int tend = (NTILES * (z + 1)) / KSPLIT;

    for (int tt = tstart; tt < tend; tt++) {
        // stage K,V tiles (64 x 32 each), coalesced
        {
            const float4* ks = (const float4*)(kbase + (size_t)tt * 64 * HD);
            const float4* vs = (const float4*)(vbase + (size_t)tt * 64 * HD);
#pragma unroll
            for (int i = t; i < 512; i += 64) {
                int r = i >> 3, c = i & 7;
                *(float4*)&Ksh[r][c * 4] = ks[i];
                *(float4*)&Vsh[r][c * 4] = vs[i];
            }
        }
        __syncthreads();

        // S = Q K^T (both row-blocks share B-frags), exp, store P
#pragma unroll
        for (int nc = 0; nc < 8; nc++) {
            float c0[2], c1[2], c2[2], c3[2];
#pragma unroll
            for (int mb = 0; mb < 2; mb++) { c0[mb] = c1[mb] = c2[mb] = c3[mb] = 0.f; }
#pragma unroll
            for (int kc = 0; kc < 4; kc++) {
                unsigned b0 = __float_as_uint(Ksh[nc * 8 + lr][kc * 8 + lc]);
                unsigned b1 = __float_as_uint(Ksh[nc * 8 + lr][kc * 8 + lc + 4]);
                mma8(c0[0], c1[0], c2[0], c3[0],
                     qa[0][kc][0], qa[0][kc][1], qa[0][kc][2], qa[0][kc][3], b0, b1);
                mma8(c0[1], c1[1], c2[1], c3[1],
                     qa[1][kc][0], qa[1][kc][1], qa[1][kc][2], qa[1][kc][3], b0, b1);
            }
#pragma unroll
            for (int mb = 0; mb < 2; mb++) {
                float p0 = tf32r(__expf(c0[mb]));
                float p1 = tf32r(__expf(c1[mb]));
                float p2 = tf32r(__expf(c2[mb]));
                float p3 = tf32r(__expf(c3[mb]));
                la[mb] += p0 + p1;   // row mb*16+lr
                lb[mb] += p2 + p3;   // row mb*16+lr+8
                *(float2*)&Psh[w][mb * 16 + lr][nc * 8 + 2 * lc] = make_float2(p0, p1);
                *(float2*)&Psh[w][mb * 16 + lr + 8][nc * 8 + 2 * lc] = make_float2(p2, p3);
            }
        }
        __syncwarp();

        // O += P V (both row-blocks share V B-frags)
#pragma unroll
        for (int kc = 0; kc < 8; kc++) {
            unsigned a[2][4];
#pragma unroll
            for (int mb = 0; mb < 2; mb++) {
                a[mb][0] = __float_as_uint(Psh[w][mb * 16 + lr][kc * 8 + lc]);
                a[mb][1] = __float_as_uint(Psh[w][mb * 16 + lr + 8][kc * 8 + lc]);
                a[mb][2] = __float_as_uint(Psh[w][mb * 16 + lr][kc * 8 + lc + 4]);
                a[mb][3] = __float_as_uint(Psh[w][mb * 16 + lr + 8][kc * 8 + lc + 4]);
            }
#pragma unroll
            for (int dc = 0; dc < 4; dc++) {
                unsigned b0 = __float_as_uint(Vsh[kc * 8 + lc][dc * 8 + lr]);
                unsigned b1 = __float_as_uint(Vsh[kc * 8 + lc + 4][dc * 8 + lr]);
                mma8(o[0][dc][0], o[0][dc][1], o[0][dc][2], o[0][dc][3],
                     a[0][0], a[0][1], a[0][2], a[0][3], b0, b1);
                mma8(o[1][dc][0], o[1][dc][1], o[1][dc][2], o[1][dc][3],
                     a[1][0], a[1][1], a[1][2], a[1][3], b0, b1);
            }
        }
        __syncthreads();
    }

    // epilogue: reduce l over the quad owning each row, write partials
#pragma unroll
    for (int mb = 0; mb < 2; mb++) {
        la[mb] += __shfl_xor_sync(0xFFFFFFFFu, la[mb], 1);
        la[mb] += __shfl_xor_sync(0xFFFFFFFFu, la[mb], 2);
        lb[mb] += __shfl_xor_sync(0xFFFFFFFFu, lb[mb], 1);
        lb[mb] += __shfl_xor_sync(0xFFFFFFFFu, lb[mb], 2);
    }

    const size_t prow = ((size_t)z * BB * HEADS + bh) * NN + nq0 + w * 32;
#pragma unroll
    for (int mb = 0; mb < 2; mb++) {
        const size_t r0 = prow + mb * 16;
        if (lc == 0) {
            g_pl[r0 + lr] = la[mb];
            g_pl[r0 + lr + 8] = lb[mb];
        }
#pragma unroll
        for (int dc = 0; dc < 4; dc++) {
            *(float2*)&g_po[(r0 + lr) * HD + dc * 8 + 2 * lc] =
                make_float2(o[mb][dc][0], o[mb][dc][1]);
            *(float2*)&g_po[(r0 + lr + 8) * HD + dc * 8 + 2 * lc] =
                make_float2(o[mb][dc][2], o[mb][dc][3]);
        }
    }
}

// =====================================================================
// Kernel 4b: combine split-K partials -> ctx [b, n, c]
// out = (sum_z o_z) / (sum_z l_z)
// =====================================================================
__global__ __launch_bounds__(256) void combine_kernel() {
    const int idx = blockIdx.x * 256 + threadIdx.x;  // over bh*NN
    if (idx >= BB * HEADS * NN) return;
    const int bh = idx / NN;
    const int n = idx % NN;

    float L = 0.f;
    float4 acc[8];
#pragma unroll
    for (int i = 0; i < 8; i++) acc[i] = make_float4(0.f, 0.f, 0.f, 0.f);
#pragma unroll 2
    for (int z = 0; z < KSPLIT; z++) {
        const size_t pidx = ((size_t)z * BB * HEADS + bh) * NN + n;
        L += g_pl[pidx];
        const float4* op = (const float4*)(g_po + pidx * HD);
#pragma unroll
        for (int i = 0; i < 8; i++) {
            float4 v = op[i];
            acc[i].x += v.x; acc[i].y += v.y;
            acc[i].z += v.z; acc[i].w += v.w;
        }
    }
    float inv = 1.f / L;
    const int b = bh / HEADS, h = bh % HEADS;
    float4* dst = (float4*)(g_ctx + ((size_t)b * NN + n) * CC + h * HD);
#pragma unroll
    for (int i = 0; i < 8; i++) {
        float4 v = acc[i];
        dst[i] = make_float4(v.x * inv, v.y * inv, v.z * inv, v.w * inv);
    }
}

// =====================================================================
// Kernel 5: proj GEMM (128x128) + bias + LayerNorm + transpose to [b,c,n]
// =====================================================================
__global__ __launch_bounds__(256) void proj_ln_kernel(const float* __restrict__ wp,
                                                      const float* __restrict__ bp,
                                                      const float* __restrict__ lg,
                                                      const float* __restrict__ lb,
                                                      float* __restrict__ out) {
    __shared__ float Csh[32][36];
    __shared__ float Wsh[32][132];
    __shared__ float Osh[32][132];
    __shared__ float mu_s[32], rs_s[32];

    const int b = blockIdx.y;
    const int n0 = blockIdx.x * 32;
    const int t = threadIdx.x;
    const int tn2 = t >> 4;
    const int to = (t & 15) * 8;

    float acc0[8], acc1[8];
#pragma unroll
    for (int u = 0; u < 8; u++) { acc0[u] = 0.f; acc1[u] = 0.f; }

    const float* ctx = g_ctx + ((size_t)b * NN + n0) * CC;

    for (int c0 = 0; c0 < CC; c0 += 32) {
        {
            int rr = t >> 3, cc4 = (t & 7) * 4;
            *(float4*)&Csh[rr][cc4] = *(const float4*)&ctx[(size_t)rr * CC + c0 + cc4];
        }
        {
            int o = t >> 1, hc = (t & 1) * 16;
#pragma unroll
            for (int u = 0; u < 4; u++) {
                float4 wv = *(const float4*)&wp[(size_t)o * CC + c0 + hc + u * 4];
                Wsh[hc + u * 4 + 0][o] = wv.x;
                Wsh[hc + u * 4 + 1][o] = wv.y;
                Wsh[hc + u * 4 + 2][o] = wv.z;
                Wsh[hc + u * 4 + 3][o] = wv.w;
            }
        }
        __syncthreads();
#pragma unroll
        for (int kk = 0; kk < 32; kk++) {
            float a0 = Csh[tn2 * 2][kk];
            float a1 = Csh[tn2 * 2 + 1][kk];
            float4 w0 = *(const float4*)&Wsh[kk][to];
            float4 w1 = *(const float4*)&Wsh[kk][to + 4];
            acc0[0] += a0 * w0.x; acc0[1] += a0 * w0.y; acc0[2] += a0 * w0.z; acc0[3] += a0 * w0.w;
            acc0[4] += a0 * w1.x; acc0[5] += a0 * w1.y; acc0[6] += a0 * w1.z; acc0[7] += a0 * w1.w;
            acc1[0] += a1 * w0.x; acc1[1] += a1 * w0.y; acc1[2] += a1 * w0.z; acc1[3] += a1 * w0.w;
            acc1[4] += a1 * w1.x; acc1[5] += a1 * w1.y; acc1[6] += a1 * w1.z; acc1[7] += a1 * w1.w;
        }
        __syncthreads();
    }

#pragma unroll
    for (int u = 0; u < 8; u++) {
        float bb = bp[to + u];
        Osh[tn2 * 2][to + u] = acc0[u] + bb;
        Osh[tn2 * 2 + 1][to + u] = acc1[u] + bb;
    }
    __syncthreads();

    {
        int wid = t >> 5, lane = t & 31;
        for (int r = wid * 4; r < wid * 4 + 4; r++) {
            float sv = 0.f, sq = 0.f;
#pragma unroll
            for (int o = 0; o < 4; o++) {
                float v = Osh[r][lane + 32 * o];
                sv += v; sq += v * v;
            }
#pragma unroll
            for (int off = 16; off; off >>= 1) {
                sv += __shfl_xor_sync(0xFFFFFFFFu, sv, off);
                sq += __shfl_xor_sync(0xFFFFFFFFu, sq, off);
            }
            if (lane == 0) {
                float mu = sv * (1.f / 128.f);
                float var = sq * (1.f / 128.f) - mu * mu;
                mu_s[r] = mu;
                rs_s[r] = rsqrtf(var + LN_EPS);
            }
        }
    }
    __syncthreads();

#pragma unroll
    for (int i = 0; i < 16; i++) {
        int e = t + 256 * i;
        int o = e >> 5, nl = e & 31;
        float v = (Osh[nl][o] - mu_s[nl]) * rs_s[nl] * lg[o] + lb[o];
        out[(size_t)(b * CC + o) * NN + n0 + nl] = v;
    }
}

// =====================================================================
extern "C" void kernel_launch(void* const* d_in, const int* in_sizes, int n_in,
                              void* d_out, int out_size) {
    const float* x      = (const float*)d_in[0];
    const float* w_qkv  = (const float*)d_in[1];
    const float* w_proj = (const float*)d_in[2];
    const float* b_proj = (const float*)d_in[3];
    const float* ln_g   = (const float*)d_in[4];
    const float* ln_b   = (const float*)d_in[5];
    float* out = (float*)d_out;

    dim3 g1(NN / 64, 384 / 64, BB);
    qkv_kernel<<<g1, 256>>>(x, w_qkv);

    pool_kernel<<<(BB * CC * AG + 255) / 256, 256>>>(x);

    dim3 g3((NN + 255) / 256, BB * HEADS);
    stage1_kernel<<<g3, 256>>>();

    dim3 g4(NN / 64, BB * HEADS, KSPLIT);
    flash_kernel<<<g4, 64>>>();

    combine_kernel<<<(BB * HEADS * NN + 255) / 256, 256>>>();

    dim3 g5(NN / 32, BB);
    proj_ln_kernel<<<g5, 256>>>(w_proj, b_proj, ln_g, ln_b, out);
}

// round 10
// speedup vs baseline: 1.0858x; 1.0858x over previous
#include <cuda_runtime.h>

#define BB 2
#define CC 128
#define HHW 56
#define NN 3136
#define HEADS 4
#define HD 32
#define AG 49
#define SCALE 0.1767766952966369f  // 32^-0.5
#define LN_EPS 1e-5f
#define KSPLIT 7
#define NTILES 49          // NN / 64

#define KP 36  // K/Q smem row pad (floats) -> conflict-free mma B/A loads
#define VP 40  // V smem row pad
#define PP 68  // P smem row pad

// ---------------- scratch (device globals; no allocation allowed) ----------------
__device__ float g_q[BB * HEADS * NN * HD];
__device__ float g_k[BB * HEADS * NN * HD];   // stored tf32-rounded
__device__ float g_v[BB * HEADS * NN * HD];   // stored tf32-rounded
__device__ float g_agent[BB * HEADS * AG * HD];
__device__ float g_qc[BB * HEADS * NN * HD];  // stored tf32-rounded, pre-scaled
__device__ float g_ctx[BB * NN * CC];
// split-K partials (no max needed: logits are tiny, exp(s) directly)
__device__ float g_po[KSPLIT * BB * HEADS * NN * HD];
__device__ float g_pl[KSPLIT * BB * HEADS * NN];

// ---------------- tf32 helpers ----------------
__device__ __forceinline__ float tf32r(float x) {
    asm("cvt.rna.tf32.f32 %0, %0;" : "+f"(x));
    return x;
}

__device__ __forceinline__ void mma8(float& c0, float& c1, float& c2, float& c3,
                                     unsigned a0, unsigned a1, unsigned a2, unsigned a3,
                                     unsigned b0, unsigned b1) {
    asm("mma.sync.aligned.m16n8k8.row.col.f32.tf32.tf32.f32 "
        "{%0,%1,%2,%3}, {%4,%5,%6,%7}, {%8,%9}, {%0,%1,%2,%3};"
        : "+f"(c0), "+f"(c1), "+f"(c2), "+f"(c3)
        : "r"(a0), "r"(a1), "r"(a2), "r"(a3), "r"(b0), "r"(b1));
}

// =====================================================================
// Kernel 1: QKV 1x1 conv via 3xTF32 tensor-core GEMM.
// Y[o,n] = sum_c W[o,c] X[c,n]; W split hi/lo, X split hi/lo,
// Y = Wh*Xh + Wh*Xl + Wl*Xh (fp32-level accuracy).
// CTA: 128 thr (4 warps, 2x2), tile 64o x 64n, K chunks of 32.
// A = W (rows o), B = X (cols n). Epilogue: smem transpose -> [n][d]
// coalesced float4 stores; k/v tf32-rounded at the source.
// =====================================================================
__global__ __launch_bounds__(128) void qkv_kernel(const float* __restrict__ x,
                                                  const float* __restrict__ w) {
    __shared__ float SB[64 * 36 * 2 + 32 * 68 * 2];  // 35840 B
    float (*Whi)[36] = (float(*)[36])SB;
    float (*Wlo)[36] = (float(*)[36])(SB + 64 * 36);
    float (*Xhi)[68] = (float(*)[68])(SB + 64 * 36 * 2);
    float (*Xlo)[68] = (float(*)[68])(SB + 64 * 36 * 2 + 32 * 68);
    float (*Osh)[68] = (float(*)[68])SB;  // overlay (after k-loop)

    const int b = blockIdx.z;
    const int o0 = blockIdx.y * 64;
    const int n0 = blockIdx.x * 64;
    const int t = threadIdx.x;
    const int wid = t >> 5;
    const int lane = t & 31;
    const int lr = lane >> 2;
    const int lc = lane & 3;
    const int wo2 = (wid >> 1) * 32;  // warp o offset in tile
    const int wn2 = (wid & 1) * 32;   // warp n offset in tile

    float c[2][4][4];
#pragma unroll
    for (int mb = 0; mb < 2; mb++)
#pragma unroll
        for (int nc = 0; nc < 4; nc++)
#pragma unroll
            for (int i = 0; i < 4; i++) c[mb][nc][i] = 0.f;

    const float* xb = x + (size_t)b * CC * NN;

    for (int k0 = 0; k0 < CC; k0 += 32) {
        // stage W 64o x 32c (hi/lo): 16 rows/pass x 4 passes, 8 lanes/row
        {
            int wrow = t >> 3, wcol = (t & 7) * 4;
#pragma unroll
            for (int u = 0; u < 4; u++) {
                int wo = wrow + u * 16;
                float4 v = *(const float4*)&w[(size_t)(o0 + wo) * CC + k0 + wcol];
                float4 h = make_float4(tf32r(v.x), tf32r(v.y), tf32r(v.z), tf32r(v.w));
                float4 l = make_float4(tf32r(v.x - h.x), tf32r(v.y - h.y),
                                       tf32r(v.z - h.z), tf32r(v.w - h.w));
                *(float4*)&Whi[wo][wcol] = h;
                *(float4*)&Wlo[wo][wcol] = l;
            }
        }
        // stage X 32c x 64n (hi/lo): 8 rows/pass x 4 passes, 16 lanes/row
        {
            int xrow = t >> 4, xcol = (t & 15) * 4;
#pragma unroll
            for (int u = 0; u < 4; u++) {
                int xc = xrow + u * 8;
                float4 v = *(const float4*)&xb[(size_t)(k0 + xc) * NN + n0 + xcol];
                float4 h = make_float4(tf32r(v.x), tf32r(v.y), tf32r(v.z), tf32r(v.w));
                float4 l = make_float4(tf32r(v.x - h.x), tf32r(v.y - h.y),
                                       tf32r(v.z - h.z), tf32r(v.w - h.w));
                *(float4*)&Xhi[xc][xcol] = h;
                *(float4*)&Xlo[xc][xcol] = l;
            }
        }
        __syncthreads();

#pragma unroll
        for (int kc = 0; kc < 4; kc++) {
            unsigned ah[2][4], al[2][4];
#pragma unroll
            for (int mb = 0; mb < 2; mb++) {
                const int r0 = wo2 + mb * 16;
                ah[mb][0] = __float_as_uint(Whi[r0 + lr][kc * 8 + lc]);
                ah[mb][1] = __float_as_uint(Whi[r0 + lr + 8][kc * 8 + lc]);
                ah[mb][2] = __float_as_uint(Whi[r0 + lr][kc * 8 + lc + 4]);
                ah[mb][3] = __float_as_uint(Whi[r0 + lr + 8][kc * 8 + lc + 4]);
                al[mb][0] = __float_as_uint(Wlo[r0 + lr][kc * 8 + lc]);
                al[mb][1] = __float_as_uint(Wlo[r0 + lr + 8][kc * 8 + lc]);
                al[mb][2] = __float_as_uint(Wlo[r0 + lr][kc * 8 + lc + 4]);
                al[mb][3] = __float_as_uint(Wlo[r0 + lr + 8][kc * 8 + lc + 4]);
            }
#pragma unroll
            for (int nc = 0; nc < 4; nc++) {
                unsigned bh0 = __float_as_uint(Xhi[kc * 8 + lc][wn2 + nc * 8 + lr]);
                unsigned bh1 = __float_as_uint(Xhi[kc * 8 + lc + 4][wn2 + nc * 8 + lr]);
                unsigned bl0 = __float_as_uint(Xlo[kc * 8 + lc][wn2 + nc * 8 + lr]);
                unsigned bl1 = __float_as_uint(Xlo[kc * 8 + lc + 4][wn2 + nc * 8 + lr]);
#pragma unroll
                for (int mb = 0; mb < 2; mb++) {
                    mma8(c[mb][nc][0], c[mb][nc][1], c[mb][nc][2], c[mb][nc][3],
                         ah[mb][0], ah[mb][1], ah[mb][2], ah[mb][3], bh0, bh1);
                    mma8(c[mb][nc][0], c[mb][nc][1], c[mb][nc][2], c[mb][nc][3],
                         ah[mb][0], ah[mb][1], ah[mb][2], ah[mb][3], bl0, bl1);
                    mma8(c[mb][nc][0], c[mb][nc][1], c[mb][nc][2], c[mb][nc][3],
                         al[mb][0], al[mb][1], al[mb][2], al[mb][3], bh0, bh1);
                }
            }
        }
        __syncthreads();
    }

    // epilogue: C frags -> Osh[o][n]
#pragma unroll
    for (int mb = 0; mb < 2; mb++) {
        const int r0 = wo2 + mb * 16;
#pragma unroll
        for (int nc = 0; nc < 4; nc++) {
            *(float2*)&Osh[r0 + lr][wn2 + nc * 8 + 2 * lc] =
                make_float2(c[mb][nc][0], c[mb][nc][1]);
            *(float2*)&Osh[r0 + lr + 8][wn2 + nc * 8 + 2 * lc] =
                make_float2(c[mb][nc][2], c[mb][nc][3]);
        }
    }
    __syncthreads();

    // writeout: [n][d] coalesced; tf32-round k/v parts
#pragma unroll
    for (int p = 0; p < 8; p++) {
        const int oh = p & 1;       // which 32-o half
        const int ng = p >> 1;      // n group of 16
        const int nrow = ng * 16 + (t >> 3);
        const int dpos = (t & 7) * 4;
        const int og = o0 + oh * 32;
        const int part = og >> 7;
        const int head = (og >> 5) & 3;
        float4 v;
        v.x = Osh[oh * 32 + dpos + 0][nrow];
        v.y = Osh[oh * 32 + dpos + 1][nrow];
        v.z = Osh[oh * 32 + dpos + 2][nrow];
        v.w = Osh[oh * 32 + dpos + 3][nrow];
        if (part != 0) {
            v.x = tf32r(v.x); v.y = tf32r(v.y);
            v.z = tf32r(v.z); v.w = tf32r(v.w);
        }
        float* dst = (part == 0) ? g_q : (part == 1) ? g_k : g_v;
        *(float4*)&dst[((size_t)(b * HEADS + head) * NN + n0 + nrow) * HD + dpos] = v;
    }
}

// =====================================================================
// Kernel 2: agent pooling — exact 8x8 block mean
// =====================================================================
__global__ void pool_kernel(const float* __restrict__ x) {
    int idx = blockIdx.x * 256 + threadIdx.x;
    if (idx >= BB * CC * AG) return;
    int a = idx % AG;
    int c = (idx / AG) % CC;
    int b = idx / (AG * CC);
    int ai = a / 7, aj = a % 7;
    const float* p = x + ((size_t)(b * CC + c) * HHW + ai * 8) * HHW + aj * 8;
    float s = 0.f;
#pragma unroll
    for (int r = 0; r < 8; r++) {
        float4 u = *(const float4*)&p[r * HHW];
        float4 u2 = *(const float4*)&p[r * HHW + 4];
        s += u.x + u.y + u.z + u.w + u2.x + u2.y + u2.z + u2.w;
    }
    s *= (1.0f / 64.0f);
    g_agent[((size_t)(b * HEADS + c / HD) * AG + a) * HD + (c % HD)] = s;
}

// =====================================================================
// Kernel 3: stage 1 — softmax over 49 agent tokens; output tf32-rounded
// and pre-scaled by SCALE (stage-2 logits).
// =====================================================================
__global__ __launch_bounds__(256) void stage1_kernel() {
    __shared__ float Ash[AG][HD];
    const int bh = blockIdx.y;
    const int n = blockIdx.x * 256 + threadIdx.x;

    {
        const float4* src = (const float4*)(g_agent + (size_t)bh * AG * HD);
        float4* dstp = (float4*)&Ash[0][0];
        for (int i = threadIdx.x; i < AG * HD / 4; i += 256) dstp[i] = src[i];
    }
    __syncthreads();
    if (n >= NN) return;

    float4 q[8];
    const float4* qp = (const float4*)(g_q + ((size_t)bh * NN + n) * HD);
#pragma unroll
    for (int i = 0; i < 8; i++) q[i] = qp[i];

    float l = 0.f;
    float4 qc[8];
#pragma unroll
    for (int i = 0; i < 8; i++) qc[i] = make_float4(0.f, 0.f, 0.f, 0.f);

#pragma unroll 7
    for (int a = 0; a < AG; a++) {
        const float4* ar = (const float4*)&Ash[a][0];
        float s = 0.f;
#pragma unroll
        for (int i = 0; i < 8; i++) {
            float4 av = ar[i];
            s += q[i].x * av.x + q[i].y * av.y + q[i].z * av.z + q[i].w * av.w;
        }
        float p = __expf(s * SCALE);  // logits tiny; no max needed
        l += p;
#pragma unroll
        for (int i = 0; i < 8; i++) {
            float4 av = ar[i];
            qc[i].x += p * av.x; qc[i].y += p * av.y;
            qc[i].z += p * av.z; qc[i].w += p * av.w;
        }
    }
    float inv = SCALE / l;
    float4* op = (float4*)(g_qc + ((size_t)bh * NN + n) * HD);
#pragma unroll
    for (int i = 0; i < 8; i++) {
        float4 v = qc[i];
        op[i] = make_float4(tf32r(v.x * inv), tf32r(v.y * inv),
                            tf32r(v.z * inv), tf32r(v.w * inv));
    }
}

// =====================================================================
// Kernel 4: stage 2 — tf32 mma flash attention, M=32 per warp.
// 64 threads = 2 warps; each warp owns 32 query rows (two m16 blocks
// that share every K/V B-fragment load). Split-K = 7 (7 tiles/split).
// Qsh overlays Psh (Q only read in prologue, fenced by staging sync).
// =====================================================================
__global__ __launch_bounds__(64) void flash_kernel() {
    __shared__ float Ksh[64][KP];
    __shared__ float Vsh[64][VP];
    __shared__ float Psh[2][32][PP];
    float (*Qsh)[KP] = (float(*)[KP])&Psh[0][0][0];  // 64x36 fits in 2x32x68

    const int bh = blockIdx.y;
    const int z = blockIdx.z;
    const int t = threadIdx.x;
    const int w = t >> 5;        // 0..1
    const int lane = t & 31;
    const int lr = lane >> 2;    // 0..7
    const int lc = lane & 3;     // 0..3
    const int nq0 = blockIdx.x * 64;

    // stage Q tile (64 x 32), coalesced
    {
        const float4* src = (const float4*)(g_qc + ((size_t)bh * NN + nq0) * HD);
#pragma unroll
        for (int i = t; i < 512; i += 64) {
            int r = i >> 3, c = i & 7;
            *(float4*)&Qsh[r][c * 4] = src[i];
        }
    }
    __syncthreads();

    // Q A-fragments: [mb][kc][reg]; warp rows w*32 + mb*16 + {lr, lr+8}
    unsigned qa[2][4][4];
#pragma unroll
    for (int mb = 0; mb < 2; mb++) {
        const int r0 = w * 32 + mb * 16;
#pragma unroll
        for (int kc = 0; kc < 4; kc++) {
            qa[mb][kc][0] = __float_as_uint(Qsh[r0 + lr][kc * 8 + lc]);
            qa[mb][kc][1] = __float_as_uint(Qsh[r0 + lr + 8][kc * 8 + lc]);
            qa[mb][kc][2] = __float_as_uint(Qsh[r0 + lr][kc * 8 + lc + 4]);
            qa[mb][kc][3] = __float_as_uint(Qsh[r0 + lr + 8][kc * 8 + lc + 4]);
        }
    }
    __syncthreads();  // Q reads done before Psh overlay is written

    float o[2][4][4];
#pragma unroll
    for (int mb = 0; mb < 2; mb++)
#pragma unroll
        for (int dc = 0; dc < 4; dc++)
#pragma unroll
            for (int i = 0; i < 4; i++) o[mb][dc][i] = 0.f;
    float la[2] = {0.f, 0.f}, lb[2] = {0.f, 0.f};

    const float* kbase = g_k + (size_t)bh * NN * HD;
    const float* vbase = g_v + (size_t)bh * NN * HD;

    const int tstart = (NTILES * z) / KSPLIT;
    const int tend = (NTILES * (z + 1)) / KSPLIT;

    for (int tt = tstart; tt < tend; tt++) {
        // stage K,V tiles (64 x 32 each), coalesced
        {
            const float4* ks = (const float4*)(kbase + (size_t)tt * 64 * HD);
            const float4* vs = (const float4*)(vbase + (size_t)tt * 64 * HD);
#pragma unroll
            for (int i = t; i < 512; i += 64) {
                int r = i >> 3, c = i & 7;
                *(float4*)&Ksh[r][c * 4] = ks[i];
                *(float4*)&Vsh[r][c * 4] = vs[i];
            }
        }
        __syncthreads();

        // S = Q K^T (both row-blocks share B-frags), exp, store P
#pragma unroll
        for (int nc = 0; nc < 8; nc++) {
            float c0[2], c1[2], c2[2], c3[2];
#pragma unroll
            for (int mb = 0; mb < 2; mb++) { c0[mb] = c1[mb] = c2[mb] = c3[mb] = 0.f; }
#pragma unroll
            for (int kc = 0; kc < 4; kc++) {
                unsigned b0 = __float_as_uint(Ksh[nc * 8 + lr][kc * 8 + lc]);
                unsigned b1 = __float_as_uint(Ksh[nc * 8 + lr][kc * 8 + lc + 4]);
                mma8(c0[0], c1[0], c2[0], c3[0],
                     qa[0][kc][0], qa[0][kc][1], qa[0][kc][2], qa[0][kc][3], b0, b1);
                mma8(c0[1], c1[1], c2[1], c3[1],
                     qa[1][kc][0], qa[1][kc][1], qa[1][kc][2], qa[1][kc][3], b0, b1);
            }
#pragma unroll
            for (int mb = 0; mb < 2; mb++) {
                float p0 = tf32r(__expf(c0[mb]));
                float p1 = tf32r(__expf(c1[mb]));
                float p2 = tf32r(__expf(c2[mb]));
                float p3 = tf32r(__expf(c3[mb]));
                la[mb] += p0 + p1;   // row mb*16+lr
                lb[mb] += p2 + p3;   // row mb*16+lr+8
                *(float2*)&Psh[w][mb * 16 + lr][nc * 8 + 2 * lc] = make_float2(p0, p1);
                *(float2*)&Psh[w][mb * 16 + lr + 8][nc * 8 + 2 * lc] = make_float2(p2, p3);
            }
        }
        __syncwarp();

        // O += P V (both row-blocks share V B-frags)
#pragma unroll
        for (int kc = 0; kc < 8; kc++) {
            unsigned a[2][4];
#pragma unroll
            for (int mb = 0; mb < 2; mb++) {
                a[mb][0] = __float_as_uint(Psh[w][mb * 16 + lr][kc * 8 + lc]);
                a[mb][1] = __float_as_uint(Psh[w][mb * 16 + lr + 8][kc * 8 + lc]);
                a[mb][2] = __float_as_uint(Psh[w][mb * 16 + lr][kc * 8 + lc + 4]);
                a[mb][3] = __float_as_uint(Psh[w][mb * 16 + lr + 8][kc * 8 + lc + 4]);
            }
#pragma unroll
            for (int dc = 0; dc < 4; dc++) {
                unsigned b0 = __float_as_uint(Vsh[kc * 8 + lc][dc * 8 + lr]);
                unsigned b1 = __float_as_uint(Vsh[kc * 8 + lc + 4][dc * 8 + lr]);
                mma8(o[0][dc][0], o[0][dc][1], o[0][dc][2], o[0][dc][3],
                     a[0][0], a[0][1], a[0][2], a[0][3], b0, b1);
                mma8(o[1][dc][0], o[1][dc][1], o[1][dc][2], o[1][dc][3],
                     a[1][0], a[1][1], a[1][2], a[1][3], b0, b1);
            }
        }
        __syncthreads();
    }

    // epilogue: reduce l over the quad owning each row, write partials
#pragma unroll
    for (int mb = 0; mb < 2; mb++) {
        la[mb] += __shfl_xor_sync(0xFFFFFFFFu, la[mb], 1);
        la[mb] += __shfl_xor_sync(0xFFFFFFFFu, la[mb], 2);
        lb[mb] += __shfl_xor_sync(0xFFFFFFFFu, lb[mb], 1);
        lb[mb] += __shfl_xor_sync(0xFFFFFFFFu, lb[mb], 2);
    }

    const size_t prow = ((size_t)z * BB * HEADS + bh) * NN + nq0 + w * 32;
#pragma unroll
    for (int mb = 0; mb < 2; mb++) {
        const size_t r0 = prow + mb * 16;
        if (lc == 0) {
            g_pl[r0 + lr] = la[mb];
            g_pl[r0 + lr + 8] = lb[mb];
        }
#pragma unroll
        for (int dc = 0; dc < 4; dc++) {
            *(float2*)&g_po[(r0 + lr) * HD + dc * 8 + 2 * lc] =
                make_float2(o[mb][dc][0], o[mb][dc][1]);
            *(float2*)&g_po[(r0 + lr + 8) * HD + dc * 8 + 2 * lc] =
                make_float2(o[mb][dc][2], o[mb][dc][3]);
        }
    }
}

// =====================================================================
// Kernel 4b: combine split-K partials -> ctx [b, n, c]
// out = (sum_z o_z) / (sum_z l_z)
// =====================================================================
__global__ __launch_bounds__(256) void combine_kernel() {
    const int idx = blockIdx.x * 256 + threadIdx.x;  // over bh*NN
    if (idx >= BB * HEADS * NN) return;
    const int bh = idx / NN;
    const int n = idx % NN;

    float L = 0.f;
    float4 acc[8];
#pragma unroll
    for (int i = 0; i < 8; i++) acc[i] = make_float4(0.f, 0.f, 0.f, 0.f);
#pragma unroll
    for (int z = 0; z < KSPLIT; z++) {
        const size_t pidx = ((size_t)z * BB * HEADS + bh) * NN + n;
        L += g_pl[pidx];
        const float4* op = (const float4*)(g_po + pidx * HD);
#pragma unroll
        for (int i = 0; i < 8; i++) {
            float4 v = op[i];
            acc[i].x += v.x; acc[i].y += v.y;
            acc[i].z += v.z; acc[i].w += v.w;
        }
    }
    float inv = 1.f / L;
    const int b = bh / HEADS, h = bh % HEADS;
    float4* dst = (float4*)(g_ctx + ((size_t)b * NN + n) * CC + h * HD);
#pragma unroll
    for (int i = 0; i < 8; i++) {
        float4 v = acc[i];
        dst[i] = make_float4(v.x * inv, v.y * inv, v.z * inv, v.w * inv);
    }
}

// =====================================================================
// Kernel 5: proj GEMM (128x128) + bias + LayerNorm + transpose to [b,c,n]
// =====================================================================
__global__ __launch_bounds__(256) void proj_ln_kernel(const float* __restrict__ wp,
                                                      const float* __restrict__ bp,
                                                      const float* __restrict__ lg,
                                                      const float* __restrict__ lb,
                                                      float* __restrict__ out) {
    __shared__ float Csh[32][36];
    __shared__ float Wsh[32][132];
    __shared__ float Osh[32][132];
    __shared__ float mu_s[32], rs_s[32];

    const int b = blockIdx.y;
    const int n0 = blockIdx.x * 32;
    const int t = threadIdx.x;
    const int tn2 = t >> 4;
    const int to = (t & 15) * 8;

    float acc0[8], acc1[8];
#pragma unroll
    for (int u = 0; u < 8; u++) { acc0[u] = 0.f; acc1[u] = 0.f; }

    const float* ctx = g_ctx + ((size_t)b * NN + n0) * CC;

    for (int c0 = 0; c0 < CC; c0 += 32) {
        {
            int rr = t >> 3, cc4 = (t & 7) * 4;
            *(float4*)&Csh[rr][cc4] = *(const float4*)&ctx[(size_t)rr * CC + c0 + cc4];
        }
        {
            int o = t >> 1, hc = (t & 1) * 16;
#pragma unroll
            for (int u = 0; u < 4; u++) {
                float4 wv = *(const float4*)&wp[(size_t)o * CC + c0 + hc + u * 4];
                Wsh[hc + u * 4 + 0][o] = wv.x;
                Wsh[hc + u * 4 + 1][o] = wv.y;
                Wsh[hc + u * 4 + 2][o] = wv.z;
                Wsh[hc + u * 4 + 3][o] = wv.w;
            }
        }
        __syncthreads();
#pragma unroll
        for (int kk = 0; kk < 32; kk++) {
            float a0 = Csh[tn2 * 2][kk];
            float a1 = Csh[tn2 * 2 + 1][kk];
            float4 w0 = *(const float4*)&Wsh[kk][to];
            float4 w1 = *(const float4*)&Wsh[kk][to + 4];
            acc0[0] += a0 * w0.x; acc0[1] += a0 * w0.y; acc0[2] += a0 * w0.z; acc0[3] += a0 * w0.w;
            acc0[4] += a0 * w1.x; acc0[5] += a0 * w1.y; acc0[6] += a0 * w1.z; acc0[7] += a0 * w1.w;
            acc1[0] += a1 * w0.x; acc1[1] += a1 * w0.y; acc1[2] += a1 * w0.z; acc1[3] += a1 * w0.w;
            acc1[4] += a1 * w1.x; acc1[5] += a1 * w1.y; acc1[6] += a1 * w1.z; acc1[7] += a1 * w1.w;
        }
        __syncthreads();
    }

#pragma unroll
    for (int u = 0; u < 8; u++) {
        float bb = bp[to + u];
        Osh[tn2 * 2][to + u] = acc0[u] + bb;
        Osh[tn2 * 2 + 1][to + u] = acc1[u] + bb;
    }
    __syncthreads();

    {
        int wid = t >> 5, lane = t & 31;
        for (int r = wid * 4; r < wid * 4 + 4; r++) {
            float sv = 0.f, sq = 0.f;
#pragma unroll
            for (int o = 0; o < 4; o++) {
                float v = Osh[r][lane + 32 * o];
                sv += v; sq += v * v;
            }
#pragma unroll
            for (int off = 16; off; off >>= 1) {
                sv += __shfl_xor_sync(0xFFFFFFFFu, sv, off);
                sq += __shfl_xor_sync(0xFFFFFFFFu, sq, off);
            }
            if (lane == 0) {
                float mu = sv * (1.f / 128.f);
                float var = sq * (1.f / 128.f) - mu * mu;
                mu_s[r] = mu;
                rs_s[r] = rsqrtf(var + LN_EPS);
            }
        }
    }
    __syncthreads();

#pragma unroll
    for (int i = 0; i < 16; i++) {
        int e = t + 256 * i;
        int o = e >> 5, nl = e & 31;
        float v = (Osh[nl][o] - mu_s[nl]) * rs_s[nl] * lg[o] + lb[o];
        out[(size_t)(b * CC + o) * NN + n0 + nl] = v;
    }
}

// =====================================================================
extern "C" void kernel_launch(void* const* d_in, const int* in_sizes, int n_in,
                              void* d_out, int out_size) {
    const float* x      = (const float*)d_in[0];
    const float* w_qkv  = (const float*)d_in[1];
    const float* w_proj = (const float*)d_in[2];
    const float* b_proj = (const float*)d_in[3];
    const float* ln_g   = (const float*)d_in[4];
    const float* ln_b   = (const float*)d_in[5];
    float* out = (float*)d_out;

    dim3 g1(NN / 64, 384 / 64, BB);
    qkv_kernel<<<g1, 128>>>(x, w_qkv);

    pool_kernel<<<(BB * CC * AG + 255) / 256, 256>>>(x);

    dim3 g3((NN + 255) / 256, BB * HEADS);
    stage1_kernel<<<g3, 256>>>();

    dim3 g4(NN / 64, BB * HEADS, KSPLIT);
    flash_kernel<<<g4, 64>>>();

    combine_kernel<<<(BB * HEADS * NN + 255) / 256, 256>>>();

    dim3 g5(NN / 32, BB);
    proj_ln_kernel<<<g5, 256>>>(w_proj, b_proj, ln_g, ln_b, out);
}

// round 12
// speedup vs baseline: 1.1418x; 1.0516x over previous
#include <cuda_runtime.h>
#include <cstdint>

#define BB 2
#define CC 128
#define HHW 56
#define NN 3136
#define HEADS 4
#define HD 32
#define AG 49
#define SCALE 0.1767766952966369f  // 32^-0.5
#define LN_EPS 1e-5f
#define KSPLIT 7
#define NTILES 49          // NN / 64

#define SP 36  // uniform smem pad (floats): conflict-free K/Q/P-A/V-B accesses

// ---------------- scratch (device globals; no allocation allowed) ----------------
__device__ float g_q[BB * HEADS * NN * HD];
__device__ float g_k[BB * HEADS * NN * HD];   // stored tf32-rounded
__device__ float g_v[BB * HEADS * NN * HD];   // stored tf32-rounded
__device__ float g_agent[BB * HEADS * AG * HD];
__device__ float g_qc[BB * HEADS * NN * HD];  // stored tf32-rounded, pre-scaled
__device__ float g_ctx[BB * NN * CC];
// split-K partials (no max needed: logits are tiny, exp(s) directly)
__device__ float g_po[KSPLIT * BB * HEADS * NN * HD];
__device__ float g_pl[KSPLIT * BB * HEADS * NN];

// ---------------- tf32 helpers ----------------
__device__ __forceinline__ float tf32r(float x) {
    asm("cvt.rna.tf32.f32 %0, %0;" : "+f"(x));
    return x;
}

__device__ __forceinline__ void mma8(float& c0, float& c1, float& c2, float& c3,
                                     unsigned a0, unsigned a1, unsigned a2, unsigned a3,
                                     unsigned b0, unsigned b1) {
    asm("mma.sync.aligned.m16n8k8.row.col.f32.tf32.tf32.f32 "
        "{%0,%1,%2,%3}, {%4,%5,%6,%7}, {%8,%9}, {%0,%1,%2,%3};"
        : "+f"(c0), "+f"(c1), "+f"(c2), "+f"(c3)
        : "r"(a0), "r"(a1), "r"(a2), "r"(a3), "r"(b0), "r"(b1));
}

__device__ __forceinline__ void cp16(unsigned smem_addr, const void* gptr) {
    asm volatile("cp.async.ca.shared.global [%0], [%1], 16;\n"
                 :: "r"(smem_addr), "l"(gptr));
}

// =====================================================================
// Kernel 1: QKV 1x1 conv via 3xTF32 tensor-core GEMM.
// =====================================================================
__global__ __launch_bounds__(128) void qkv_kernel(const float* __restrict__ x,
                                                  const float* __restrict__ w) {
    __shared__ float SB[64 * 36 * 2 + 32 * 68 * 2];  // 35840 B
    float (*Whi)[36] = (float(*)[36])SB;
    float (*Wlo)[36] = (float(*)[36])(SB + 64 * 36);
    float (*Xhi)[68] = (float(*)[68])(SB + 64 * 36 * 2);
    float (*Xlo)[68] = (float(*)[68])(SB + 64 * 36 * 2 + 32 * 68);
    float (*Osh)[68] = (float(*)[68])SB;  // overlay (after k-loop)

    const int b = blockIdx.z;
    const int o0 = blockIdx.y * 64;
    const int n0 = blockIdx.x * 64;
    const int t = threadIdx.x;
    const int wid = t >> 5;
    const int lane = t & 31;
    const int lr = lane >> 2;
    const int lc = lane & 3;
    const int wo2 = (wid >> 1) * 32;  // warp o offset in tile
    const int wn2 = (wid & 1) * 32;   // warp n offset in tile

    float c[2][4][4];
#pragma unroll
    for (int mb = 0; mb < 2; mb++)
#pragma unroll
        for (int nc = 0; nc < 4; nc++)
#pragma unroll
            for (int i = 0; i < 4; i++) c[mb][nc][i] = 0.f;

    const float* xb = x + (size_t)b * CC * NN;

    for (int k0 = 0; k0 < CC; k0 += 32) {
        {
            int wrow = t >> 3, wcol = (t & 7) * 4;
#pragma unroll
            for (int u = 0; u < 4; u++) {
                int wo = wrow + u * 16;
                float4 v = *(const float4*)&w[(size_t)(o0 + wo) * CC + k0 + wcol];
                float4 h = make_float4(tf32r(v.x), tf32r(v.y), tf32r(v.z), tf32r(v.w));
                float4 l = make_float4(tf32r(v.x - h.x), tf32r(v.y - h.y),
                                       tf32r(v.z - h.z), tf32r(v.w - h.w));
                *(float4*)&Whi[wo][wcol] = h;
                *(float4*)&Wlo[wo][wcol] = l;
            }
        }
        {
            int xrow = t >> 4, xcol = (t & 15) * 4;
#pragma unroll
            for (int u = 0; u < 4; u++) {
                int xc = xrow + u * 8;
                float4 v = *(const float4*)&xb[(size_t)(k0 + xc) * NN + n0 + xcol];
                float4 h = make_float4(tf32r(v.x), tf32r(v.y), tf32r(v.z), tf32r(v.w));
                float4 l = make_float4(tf32r(v.x - h.x), tf32r(v.y - h.y),
                                       tf32r(v.z - h.z), tf32r(v.w - h.w));
                *(float4*)&Xhi[xc][xcol] = h;
                *(float4*)&Xlo[xc][xcol] = l;
            }
        }
        __syncthreads();

#pragma unroll
        for (int kc = 0; kc < 4; kc++) {
            unsigned ah[2][4], al[2][4];
#pragma unroll
            for (int mb = 0; mb < 2; mb++) {
                const int r0 = wo2 + mb * 16;
                ah[mb][0] = __float_as_uint(Whi[r0 + lr][kc * 8 + lc]);
                ah[mb][1] = __float_as_uint(Whi[r0 + lr + 8][kc * 8 + lc]);
                ah[mb][2] = __float_as_uint(Whi[r0 + lr][kc * 8 + lc + 4]);
                ah[mb][3] = __float_as_uint(Whi[r0 + lr + 8][kc * 8 + lc + 4]);
                al[mb][0] = __float_as_uint(Wlo[r0 + lr][kc * 8 + lc]);
                al[mb][1] = __float_as_uint(Wlo[r0 + lr + 8][kc * 8 + lc]);
                al[mb][2] = __float_as_uint(Wlo[r0 + lr][kc * 8 + lc + 4]);
                al[mb][3] = __float_as_uint(Wlo[r0 + lr + 8][kc * 8 + lc + 4]);
            }
#pragma unroll
            for (int nc = 0; nc < 4; nc++) {
                unsigned bh0 = __float_as_uint(Xhi[kc * 8 + lc][wn2 + nc * 8 + lr]);
                unsigned bh1 = __float_as_uint(Xhi[kc * 8 + lc + 4][wn2 + nc * 8 + lr]);
                unsigned bl0 = __float_as_uint(Xlo[kc * 8 + lc][wn2 + nc * 8 + lr]);
                unsigned bl1 = __float_as_uint(Xlo[kc * 8 + lc + 4][wn2 + nc * 8 + lr]);
#pragma unroll
                for (int mb = 0; mb < 2; mb++) {
                    mma8(c[mb][nc][0], c[mb][nc][1], c[mb][nc][2], c[mb][nc][3],
                         ah[mb][0], ah[mb][1], ah[mb][2], ah[mb][3], bh0, bh1);
                    mma8(c[mb][nc][0], c[mb][nc][1], c[mb][nc][2], c[mb][nc][3],
                         ah[mb][0], ah[mb][1], ah[mb][2], ah[mb][3], bl0, bl1);
                    mma8(c[mb][nc][0], c[mb][nc][1], c[mb][nc][2], c[mb][nc][3],
                         al[mb][0], al[mb][1], al[mb][2], al[mb][3], bh0, bh1);
                }
            }
        }
        __syncthreads();
    }

#pragma unroll
    for (int mb = 0; mb < 2; mb++) {
        const int r0 = wo2 + mb * 16;
#pragma unroll
        for (int nc = 0; nc < 4; nc++) {
            *(float2*)&Osh[r0 + lr][wn2 + nc * 8 + 2 * lc] =
                make_float2(c[mb][nc][0], c[mb][nc][1]);
            *(float2*)&Osh[r0 + lr + 8][wn2 + nc * 8 + 2 * lc] =
                make_float2(c[mb][nc][2], c[mb][nc][3]);
        }
    }
    __syncthreads();

#pragma unroll
    for (int p = 0; p < 8; p++) {
        const int oh = p & 1;
        const int ng = p >> 1;
        const int nrow = ng * 16 + (t >> 3);
        const int dpos = (t & 7) * 4;
        const int og = o0 + oh * 32;
        const int part = og >> 7;
        const int head = (og >> 5) & 3;
        float4 v;
        v.x = Osh[oh * 32 + dpos + 0][nrow];
        v.y = Osh[oh * 32 + dpos + 1][nrow];
        v.z = Osh[oh * 32 + dpos + 2][nrow];
        v.w = Osh[oh * 32 + dpos + 3][nrow];
        if (part != 0) {
            v.x = tf32r(v.x); v.y = tf32r(v.y);
            v.z = tf32r(v.z); v.w = tf32r(v.w);
        }
        float* dst = (part == 0) ? g_q : (part == 1) ? g_k : g_v;
        *(float4*)&dst[((size_t)(b * HEADS + head) * NN + n0 + nrow) * HD + dpos] = v;
    }
}

// =====================================================================
// Kernel 2: agent pooling — exact 8x8 block mean
// =====================================================================
__global__ void pool_kernel(const float* __restrict__ x) {
    int idx = blockIdx.x * 256 + threadIdx.x;
    if (idx >= BB * CC * AG) return;
    int a = idx % AG;
    int c = (idx / AG) % CC;
    int b = idx / (AG * CC);
    int ai = a / 7, aj = a % 7;
    const float* p = x + ((size_t)(b * CC + c) * HHW + ai * 8) * HHW + aj * 8;
    float s = 0.f;
#pragma unroll
    for (int r = 0; r < 8; r++) {
        float4 u = *(const float4*)&p[r * HHW];
        float4 u2 = *(const float4*)&p[r * HHW + 4];
        s += u.x + u.y + u.z + u.w + u2.x + u2.y + u2.z + u2.w;
    }
    s *= (1.0f / 64.0f);
    g_agent[((size_t)(b * HEADS + c / HD) * AG + a) * HD + (c % HD)] = s;
}

// =====================================================================
// Kernel 3: stage 1 — softmax over 49 agent tokens; output tf32-rounded
// and pre-scaled by SCALE (stage-2 logits).
// =====================================================================
__global__ __launch_bounds__(256) void stage1_kernel() {
    __shared__ float Ash[AG][HD];
    const int bh = blockIdx.y;
    const int n = blockIdx.x * 256 + threadIdx.x;

    {
        const float4* src = (const float4*)(g_agent + (size_t)bh * AG * HD);
        float4* dstp = (float4*)&Ash[0][0];
        for (int i = threadIdx.x; i < AG * HD / 4; i += 256) dstp[i] = src[i];
    }
    __syncthreads();
    if (n >= NN) return;

    float4 q[8];
    const float4* qp = (const float4*)(g_q + ((size_t)bh * NN + n) * HD);
#pragma unroll
    for (int i = 0; i < 8; i++) q[i] = qp[i];

    float l = 0.f;
    float4 qc[8];
#pragma unroll
    for (int i = 0; i < 8; i++) qc[i] = make_float4(0.f, 0.f, 0.f, 0.f);

#pragma unroll 7
    for (int a = 0; a < AG; a++) {
        const float4* ar = (const float4*)&Ash[a][0];
        float s = 0.f;
#pragma unroll
        for (int i = 0; i < 8; i++) {
            float4 av = ar[i];
            s += q[i].x * av.x + q[i].y * av.y + q[i].z * av.z + q[i].w * av.w;
        }
        float p = __expf(s * SCALE);  // logits tiny; no max needed
        l += p;
#pragma unroll
        for (int i = 0; i < 8; i++) {
            float4 av = ar[i];
            qc[i].x += p * av.x; qc[i].y += p * av.y;
            qc[i].z += p * av.z; qc[i].w += p * av.w;
        }
    }
    float inv = SCALE / l;
    float4* op = (float4*)(g_qc + ((size_t)bh * NN + n) * HD);
#pragma unroll
    for (int i = 0; i < 8; i++) {
        float4 v = qc[i];
        op[i] = make_float4(tf32r(v.x * inv), tf32r(v.y * inv),
                            tf32r(v.z * inv), tf32r(v.w * inv));
    }
}

// =====================================================================
// Kernel 4: stage 2 — tf32 mma flash attention, M=32 per warp,
// keys processed in two 32-key halves (Psh 2x32x36 = 9KB), cp.async
// staging (no register staging buffers), all pads 36 (conflict-free
// frag loads). smem 27KB -> 8 CTAs/SM; launch_bounds(64,8) -> <=128
// regs -> 16 warps/SM.
// =====================================================================
__global__ __launch_bounds__(64, 8) void flash_kernel() {
    __shared__ float Ksh[64][SP];
    __shared__ float Vsh[64][SP];
    __shared__ float Psh[2][32][SP];
    float (*Qsh)[SP] = (float(*)[SP])&Psh[0][0][0];  // 64x36 == 2x32x36

    const int bh = blockIdx.y;
    const int z = blockIdx.z;
    const int t = threadIdx.x;
    const int w = t >> 5;        // 0..1
    const int lane = t & 31;
    const int lr = lane >> 2;    // 0..7
    const int lc = lane & 3;     // 0..3
    const int nq0 = blockIdx.x * 64;

    // stage Q tile (64 x 32), coalesced
    {
        const float4* src = (const float4*)(g_qc + ((size_t)bh * NN + nq0) * HD);
#pragma unroll
        for (int i = t; i < 512; i += 64) {
            int r = i >> 3, c = i & 7;
            *(float4*)&Qsh[r][c * 4] = src[i];
        }
    }
    __syncthreads();

    // Q A-fragments: [mb][kc][reg]; warp rows w*32 + mb*16 + {lr, lr+8}
    unsigned qa[2][4][4];
#pragma unroll
    for (int mb = 0; mb < 2; mb++) {
        const int r0 = w * 32 + mb * 16;
#pragma unroll
        for (int kc = 0; kc < 4; kc++) {
            qa[mb][kc][0] = __float_as_uint(Qsh[r0 + lr][kc * 8 + lc]);
            qa[mb][kc][1] = __float_as_uint(Qsh[r0 + lr + 8][kc * 8 + lc]);
            qa[mb][kc][2] = __float_as_uint(Qsh[r0 + lr][kc * 8 + lc + 4]);
            qa[mb][kc][3] = __float_as_uint(Qsh[r0 + lr + 8][kc * 8 + lc + 4]);
        }
    }
    __syncthreads();  // Q reads done before Psh overlay is written

    float o[2][4][4];
#pragma unroll
    for (int mb = 0; mb < 2; mb++)
#pragma unroll
        for (int dc = 0; dc < 4; dc++)
#pragma unroll
            for (int i = 0; i < 4; i++) o[mb][dc][i] = 0.f;
    float la[2] = {0.f, 0.f}, lb[2] = {0.f, 0.f};

    const float* kbase = g_k + (size_t)bh * NN * HD;
    const float* vbase = g_v + (size_t)bh * NN * HD;

    const unsigned ksh0 = (unsigned)__cvta_generic_to_shared(&Ksh[0][0]);
    const unsigned vsh0 = (unsigned)__cvta_generic_to_shared(&Vsh[0][0]);

    const int tstart = (NTILES * z) / KSPLIT;
    const int tend = (NTILES * (z + 1)) / KSPLIT;

    for (int tt = tstart; tt < tend; tt++) {
        // stage K,V tiles (64 x 32 each) via cp.async
        {
            const float4* ks = (const float4*)(kbase + (size_t)tt * 64 * HD);
            const float4* vs = (const float4*)(vbase + (size_t)tt * 64 * HD);
#pragma unroll
            for (int i = t; i < 512; i += 64) {
                int r = i >> 3, c = i & 7;
                cp16(ksh0 + (r * SP + c * 4) * 4, ks + i);
                cp16(vsh0 + (r * SP + c * 4) * 4, vs + i);
            }
            asm volatile("cp.async.commit_group;\n");
            asm volatile("cp.async.wait_group 0;\n" ::: "memory");
        }
        __syncthreads();

#pragma unroll
        for (int kh = 0; kh < 2; kh++) {
            // S = Q K^T for 32-key half, exp, store P
#pragma unroll
            for (int nc = 0; nc < 4; nc++) {
                const int krow = kh * 32 + nc * 8 + lr;
                float c0[2], c1[2], c2[2], c3[2];
#pragma unroll
                for (int mb = 0; mb < 2; mb++) { c0[mb] = c1[mb] = c2[mb] = c3[mb] = 0.f; }
#pragma unroll
                for (int kc = 0; kc < 4; kc++) {
                    unsigned b0 = __float_as_uint(Ksh[krow][kc * 8 + lc]);
                    unsigned b1 = __float_as_uint(Ksh[krow][kc * 8 + lc + 4]);
                    mma8(c0[0], c1[0], c2[0], c3[0],
                         qa[0][kc][0], qa[0][kc][1], qa[0][kc][2], qa[0][kc][3], b0, b1);
                    mma8(c0[1], c1[1], c2[1], c3[1],
                         qa[1][kc][0], qa[1][kc][1], qa[1][kc][2], qa[1][kc][3], b0, b1);
                }
#pragma unroll
                for (int mb = 0; mb < 2; mb++) {
                    float p0 = tf32r(__expf(c0[mb]));
                    float p1 = tf32r(__expf(c1[mb]));
                    float p2 = tf32r(__expf(c2[mb]));
                    float p3 = tf32r(__expf(c3[mb]));
                    la[mb] += p0 + p1;   // row mb*16+lr
                    lb[mb] += p2 + p3;   // row mb*16+lr+8
                    *(float2*)&Psh[w][mb * 16 + lr][nc * 8 + 2 * lc] = make_float2(p0, p1);
                    *(float2*)&Psh[w][mb * 16 + lr + 8][nc * 8 + 2 * lc] = make_float2(p2, p3);
                }
            }
            __syncwarp();

            // O += P V for this half (both row-blocks share V B-frags)
#pragma unroll
            for (int kc = 0; kc < 4; kc++) {
                unsigned a[2][4];
#pragma unroll
                for (int mb = 0; mb < 2; mb++) {
                    a[mb][0] = __float_as_uint(Psh[w][mb * 16 + lr][kc * 8 + lc]);
                    a[mb][1] = __float_as_uint(Psh[w][mb * 16 + lr + 8][kc * 8 + lc]);
                    a[mb][2] = __float_as_uint(Psh[w][mb * 16 + lr][kc * 8 + lc + 4]);
                    a[mb][3] = __float_as_uint(Psh[w][mb * 16 + lr + 8][kc * 8 + lc + 4]);
                }
                const int vrow = kh * 32 + kc * 8;
#pragma unroll
                for (int dc = 0; dc < 4; dc++) {
                    unsigned b0 = __float_as_uint(Vsh[vrow + lc][dc * 8 + lr]);
                    unsigned b1 = __float_as_uint(Vsh[vrow + lc + 4][dc * 8 + lr]);
                    mma8(o[0][dc][0], o[0][dc][1], o[0][dc][2], o[0][dc][3],
                         a[0][0], a[0][1], a[0][2], a[0][3], b0, b1);
                    mma8(o[1][dc][0], o[1][dc][1], o[1][dc][2], o[1][dc][3],
                         a[1][0], a[1][1], a[1][2], a[1][3], b0, b1);
                }
            }
            __syncwarp();  // Psh reads done before next half overwrites
        }
        __syncthreads();   // K/V reads done before next tile staging
    }

    // epilogue: reduce l over the quad owning each row, write partials
#pragma unroll
    for (int mb = 0; mb < 2; mb++) {
        la[mb] += __shfl_xor_sync(0xFFFFFFFFu, la[mb], 1);
        la[mb] += __shfl_xor_sync(0xFFFFFFFFu, la[mb], 2);
        lb[mb] += __shfl_xor_sync(0xFFFFFFFFu, lb[mb], 1);
        lb[mb] += __shfl_xor_sync(0xFFFFFFFFu, lb[mb], 2);
    }

    const size_t prow = ((size_t)z * BB * HEADS + bh) * NN + nq0 + w * 32;
#pragma unroll
    for (int mb = 0; mb < 2; mb++) {
        const size_t r0 = prow + mb * 16;
        if (lc == 0) {
            g_pl[r0 + lr] = la[mb];
            g_pl[r0 + lr + 8] = lb[mb];
        }
#pragma unroll
        for (int dc = 0; dc < 4; dc++) {
            *(float2*)&g_po[(r0 + lr) * HD + dc * 8 + 2 * lc] =
                make_float2(o[mb][dc][0], o[mb][dc][1]);
            *(float2*)&g_po[(r0 + lr + 8) * HD + dc * 8 + 2 * lc] =
                make_float2(o[mb][dc][2], o[mb][dc][3]);
        }
    }
}

// =====================================================================
// Kernel 4b: combine split-K partials -> ctx [b, n, c]
// =====================================================================
__global__ __launch_bounds__(256) void combine_kernel() {
    const int idx = blockIdx.x * 256 + threadIdx.x;  // over bh*NN
    if (idx >= BB * HEADS * NN) return;
    const int bh = idx / NN;
    const int n = idx % NN;

    float L = 0.f;
    float4 acc[8];
#pragma unroll
    for (int i = 0; i < 8; i++) acc[i] = make_float4(0.f, 0.f, 0.f, 0.f);
#pragma unroll
    for (int z = 0; z < KSPLIT; z++) {
        const size_t pidx = ((size_t)z * BB * HEADS + bh) * NN + n;
        L += g_pl[pidx];
        const float4* op = (const float4*)(g_po + pidx * HD);
#pragma unroll
        for (int i = 0; i < 8; i++) {
            float4 v = op[i];
            acc[i].x += v.x; acc[i].y += v.y;
            acc[i].z += v.z; acc[i].w += v.w;
        }
    }
    float inv = 1.f / L;
    const int b = bh / HEADS, h = bh % HEADS;
    float4* dst = (float4*)(g_ctx + ((size_t)b * NN + n) * CC + h * HD);
#pragma unroll
    for (int i = 0; i < 8; i++) {
        float4 v = acc[i];
        dst[i] = make_float4(v.x * inv, v.y * inv, v.z * inv, v.w * inv);
    }
}

// =====================================================================
// Kernel 5: proj GEMM (128x128) + bias + LayerNorm + transpose to [b,c,n]
// =====================================================================
__global__ __launch_bounds__(256) void proj_ln_kernel(const float* __restrict__ wp,
                                                      const float* __restrict__ bp,
                                                      const float* __restrict__ lg,
                                                      const float* __restrict__ lb,
                                                      float* __restrict__ out) {
    __shared__ float Csh[32][36];
    __shared__ float Wsh[32][132];
    __shared__ float Osh[32][132];
    __shared__ float mu_s[32], rs_s[32];

    const int b = blockIdx.y;
    const int n0 = blockIdx.x * 32;
    const int t = threadIdx.x;
    const int tn2 = t >> 4;
    const int to = (t & 15) * 8;

    float acc0[8], acc1[8];
#pragma unroll
    for (int u = 0; u < 8; u++) { acc0[u] = 0.f; acc1[u] = 0.f; }

    const float* ctx = g_ctx + ((size_t)b * NN + n0) * CC;

    for (int c0 = 0; c0 < CC; c0 += 32) {
        {
            int rr = t >> 3, cc4 = (t & 7) * 4;
            *(float4*)&Csh[rr][cc4] = *(const float4*)&ctx[(size_t)rr * CC + c0 + cc4];
        }
        {
            int o = t >> 1, hc = (t & 1) * 16;
#pragma unroll
            for (int u = 0; u < 4; u++) {
                float4 wv = *(const float4*)&wp[(size_t)o * CC + c0 + hc + u * 4];
                Wsh[hc + u * 4 + 0][o] = wv.x;
                Wsh[hc + u * 4 + 1][o] = wv.y;
                Wsh[hc + u * 4 + 2][o] = wv.z;
                Wsh[hc + u * 4 + 3][o] = wv.w;
            }
        }
        __syncthreads();
#pragma unroll
        for (int kk = 0; kk < 32; kk++) {
            float a0 = Csh[tn2 * 2][kk];
            float a1 = Csh[tn2 * 2 + 1][kk];
            float4 w0 = *(const float4*)&Wsh[kk][to];
            float4 w1 = *(const float4*)&Wsh[kk][to + 4];
            acc0[0] += a0 * w0.x; acc0[1] += a0 * w0.y; acc0[2] += a0 * w0.z; acc0[3] += a0 * w0.w;
            acc0[4] += a0 * w1.x; acc0[5] += a0 * w1.y; acc0[6] += a0 * w1.z; acc0[7] += a0 * w1.w;
            acc1[0] += a1 * w0.x; acc1[1] += a1 * w0.y; acc1[2] += a1 * w0.z; acc1[3] += a1 * w0.w;
            acc1[4] += a1 * w1.x; acc1[5] += a1 * w1.y; acc1[6] += a1 * w1.z; acc1[7] += a1 * w1.w;
        }
        __syncthreads();
    }

#pragma unroll
    for (int u = 0; u < 8; u++) {
        float bb = bp[to + u];
        Osh[tn2 * 2][to + u] = acc0[u] + bb;
        Osh[tn2 * 2 + 1][to + u] = acc1[u] + bb;
    }
    __syncthreads();

    {
        int wid = t >> 5, lane = t & 31;
        for (int r = wid * 4; r < wid * 4 + 4; r++) {
            float sv = 0.f, sq = 0.f;
#pragma unroll
            for (int o = 0; o < 4; o++) {
                float v = Osh[r][lane + 32 * o];
                sv += v; sq += v * v;
            }
#pragma unroll
            for (int off = 16; off; off >>= 1) {
                sv += __shfl_xor_sync(0xFFFFFFFFu, sv, off);
                sq += __shfl_xor_sync(0xFFFFFFFFu, sq, off);
            }
            if (lane == 0) {
                float mu = sv * (1.f / 128.f);
                float var = sq * (1.f / 128.f) - mu * mu;
                mu_s[r] = mu;
                rs_s[r] = rsqrtf(var + LN_EPS);
            }
        }
    }
    __syncthreads();

#pragma unroll
    for (int i = 0; i < 16; i++) {
        int e = t + 256 * i;
        int o = e >> 5, nl = e & 31;
        float v = (Osh[nl][o] - mu_s[nl]) * rs_s[nl] * lg[o] + lb[o];
        out[(size_t)(b * CC + o) * NN + n0 + nl] = v;
    }
}

// =====================================================================
extern "C" void kernel_launch(void* const* d_in, const int* in_sizes, int n_in,
                              void* d_out, int out_size) {
    const float* x      = (const float*)d_in[0];
    const float* w_qkv  = (const float*)d_in[1];
    const float* w_proj = (const float*)d_in[2];
    const float* b_proj = (const float*)d_in[3];
    const float* ln_g   = (const float*)d_in[4];
    const float* ln_b   = (const float*)d_in[5];
    float* out = (float*)d_out;

    dim3 g1(NN / 64, 384 / 64, BB);
    qkv_kernel<<<g1, 128>>>(x, w_qkv);

    pool_kernel<<<(BB * CC * AG + 255) / 256, 256>>>(x);

    dim3 g3((NN + 255) / 256, BB * HEADS);
    stage1_kernel<<<g3, 256>>>();

    dim3 g4(NN / 64, BB * HEADS, KSPLIT);
    flash_kernel<<<g4, 64>>>();

    combine_kernel<<<(BB * HEADS * NN + 255) / 256, 256>>>();

    dim3 g5(NN / 32, BB);
    proj_ln_kernel<<<g5, 256>>>(w_proj, b_proj, ln_g, ln_b, out);
}

// round 14
// speedup vs baseline: 1.2739x; 1.1157x over previous
#include <cuda_runtime.h>
#include <cstdint>

#define BB 2
#define CC 128
#define HHW 56
#define NN 3136
#define HEADS 4
#define HD 32
#define AG 49
#define SCALE 0.1767766952966369f  // 32^-0.5
#define LN_EPS 1e-5f
#define KSPLIT 7
#define NTILES 49          // NN / 64

#define SP 36  // uniform smem pad (floats): conflict-free K/Q/P-A/V-B accesses
#define PO 133 // proj LN epilogue pad: gcd(5,32)=1 -> conflict-free column reads

// ---------------- scratch (device globals; no allocation allowed) ----------------
__device__ float g_q[BB * HEADS * NN * HD];
__device__ float g_k[BB * HEADS * NN * HD];   // stored tf32-rounded
__device__ float g_v[BB * HEADS * NN * HD];   // stored tf32-rounded
__device__ float g_agent[BB * HEADS * AG * HD];
__device__ float g_qc[BB * HEADS * NN * HD];  // stored tf32-rounded, pre-scaled
__device__ float g_ctx[BB * NN * CC];
// split-K partials (no max needed: logits are tiny, exp(s) directly)
__device__ float g_po[KSPLIT * BB * HEADS * NN * HD];
__device__ float g_pl[KSPLIT * BB * HEADS * NN];

// ---------------- tf32 helpers ----------------
__device__ __forceinline__ float tf32r(float x) {
    asm("cvt.rna.tf32.f32 %0, %0;" : "+f"(x));
    return x;
}

__device__ __forceinline__ void mma8(float& c0, float& c1, float& c2, float& c3,
                                     unsigned a0, unsigned a1, unsigned a2, unsigned a3,
                                     unsigned b0, unsigned b1) {
    asm("mma.sync.aligned.m16n8k8.row.col.f32.tf32.tf32.f32 "
        "{%0,%1,%2,%3}, {%4,%5,%6,%7}, {%8,%9}, {%0,%1,%2,%3};"
        : "+f"(c0), "+f"(c1), "+f"(c2), "+f"(c3)
        : "r"(a0), "r"(a1), "r"(a2), "r"(a3), "r"(b0), "r"(b1));
}

__device__ __forceinline__ void cp16(unsigned smem_addr, const void* gptr) {
    asm volatile("cp.async.ca.shared.global [%0], [%1], 16;\n"
                 :: "r"(smem_addr), "l"(gptr));
}

// =====================================================================
// Kernel 1: QKV 1x1 conv via 3xTF32 tensor-core GEMM.
// =====================================================================
__global__ __launch_bounds__(128) void qkv_kernel(const float* __restrict__ x,
                                                  const float* __restrict__ w) {
    __shared__ float SB[64 * 36 * 2 + 32 * 68 * 2];  // 35840 B
    float (*Whi)[36] = (float(*)[36])SB;
    float (*Wlo)[36] = (float(*)[36])(SB + 64 * 36);
    float (*Xhi)[68] = (float(*)[68])(SB + 64 * 36 * 2);
    float (*Xlo)[68] = (float(*)[68])(SB + 64 * 36 * 2 + 32 * 68);
    float (*Osh)[68] = (float(*)[68])SB;  // overlay (after k-loop)

    const int b = blockIdx.z;
    const int o0 = blockIdx.y * 64;
    const int n0 = blockIdx.x * 64;
    const int t = threadIdx.x;
    const int wid = t >> 5;
    const int lane = t & 31;
    const int lr = lane >> 2;
    const int lc = lane & 3;
    const int wo2 = (wid >> 1) * 32;  // warp o offset in tile
    const int wn2 = (wid & 1) * 32;   // warp n offset in tile

    float c[2][4][4];
#pragma unroll
    for (int mb = 0; mb < 2; mb++)
#pragma unroll
        for (int nc = 0; nc < 4; nc++)
#pragma unroll
            for (int i = 0; i < 4; i++) c[mb][nc][i] = 0.f;

    const float* xb = x + (size_t)b * CC * NN;

    for (int k0 = 0; k0 < CC; k0 += 32) {
        {
            int wrow = t >> 3, wcol = (t & 7) * 4;
#pragma unroll
            for (int u = 0; u < 4; u++) {
                int wo = wrow + u * 16;
                float4 v = *(const float4*)&w[(size_t)(o0 + wo) * CC + k0 + wcol];
                float4 h = make_float4(tf32r(v.x), tf32r(v.y), tf32r(v.z), tf32r(v.w));
                float4 l = make_float4(tf32r(v.x - h.x), tf32r(v.y - h.y),
                                       tf32r(v.z - h.z), tf32r(v.w - h.w));
                *(float4*)&Whi[wo][wcol] = h;
                *(float4*)&Wlo[wo][wcol] = l;
            }
        }
        {
            int xrow = t >> 4, xcol = (t & 15) * 4;
#pragma unroll
            for (int u = 0; u < 4; u++) {
                int xc = xrow + u * 8;
                float4 v = *(const float4*)&xb[(size_t)(k0 + xc) * NN + n0 + xcol];
                float4 h = make_float4(tf32r(v.x), tf32r(v.y), tf32r(v.z), tf32r(v.w));
                float4 l = make_float4(tf32r(v.x - h.x), tf32r(v.y - h.y),
                                       tf32r(v.z - h.z), tf32r(v.w - h.w));
                *(float4*)&Xhi[xc][xcol] = h;
                *(float4*)&Xlo[xc][xcol] = l;
            }
        }
        __syncthreads();

#pragma unroll
        for (int kc = 0; kc < 4; kc++) {
            unsigned ah[2][4], al[2][4];
#pragma unroll
            for (int mb = 0; mb < 2; mb++) {
                const int r0 = wo2 + mb * 16;
                ah[mb][0] = __float_as_uint(Whi[r0 + lr][kc * 8 + lc]);
                ah[mb][1] = __float_as_uint(Whi[r0 + lr + 8][kc * 8 + lc]);
                ah[mb][2] = __float_as_uint(Whi[r0 + lr][kc * 8 + lc + 4]);
                ah[mb][3] = __float_as_uint(Whi[r0 + lr + 8][kc * 8 + lc + 4]);
                al[mb][0] = __float_as_uint(Wlo[r0 + lr][kc * 8 + lc]);
                al[mb][1] = __float_as_uint(Wlo[r0 + lr + 8][kc * 8 + lc]);
                al[mb][2] = __float_as_uint(Wlo[r0 + lr][kc * 8 + lc + 4]);
                al[mb][3] = __float_as_uint(Wlo[r0 + lr + 8][kc * 8 + lc + 4]);
            }
#pragma unroll
            for (int nc = 0; nc < 4; nc++) {
                unsigned bh0 = __float_as_uint(Xhi[kc * 8 + lc][wn2 + nc * 8 + lr]);
                unsigned bh1 = __float_as_uint(Xhi[kc * 8 + lc + 4][wn2 + nc * 8 + lr]);
                unsigned bl0 = __float_as_uint(Xlo[kc * 8 + lc][wn2 + nc * 8 + lr]);
                unsigned bl1 = __float_as_uint(Xlo[kc * 8 + lc + 4][wn2 + nc * 8 + lr]);
#pragma unroll
                for (int mb = 0; mb < 2; mb++) {
                    mma8(c[mb][nc][0], c[mb][nc][1], c[mb][nc][2], c[mb][nc][3],
                         ah[mb][0], ah[mb][1], ah[mb][2], ah[mb][3], bh0, bh1);
                    mma8(c[mb][nc][0], c[mb][nc][1], c[mb][nc][2], c[mb][nc][3],
                         ah[mb][0], ah[mb][1], ah[mb][2], ah[mb][3], bl0, bl1);
                    mma8(c[mb][nc][0], c[mb][nc][1], c[mb][nc][2], c[mb][nc][3],
                         al[mb][0], al[mb][1], al[mb][2], al[mb][3], bh0, bh1);
                }
            }
        }
        __syncthreads();
    }

#pragma unroll
    for (int mb = 0; mb < 2; mb++) {
        const int r0 = wo2 + mb * 16;
#pragma unroll
        for (int nc = 0; nc < 4; nc++) {
            *(float2*)&Osh[r0 + lr][wn2 + nc * 8 + 2 * lc] =
                make_float2(c[mb][nc][0], c[mb][nc][1]);
            *(float2*)&Osh[r0 + lr + 8][wn2 + nc * 8 + 2 * lc] =
                make_float2(c[mb][nc][2], c[mb][nc][3]);
        }
    }
    __syncthreads();

#pragma unroll
    for (int p = 0; p < 8; p++) {
        const int oh = p & 1;
        const int ng = p >> 1;
        const int nrow = ng * 16 + (t >> 3);
        const int dpos = (t & 7) * 4;
        const int og = o0 + oh * 32;
        const int part = og >> 7;
        const int head = (og >> 5) & 3;
        float4 v;
        v.x = Osh[oh * 32 + dpos + 0][nrow];
        v.y = Osh[oh * 32 + dpos + 1][nrow];
        v.z = Osh[oh * 32 + dpos + 2][nrow];
        v.w = Osh[oh * 32 + dpos + 3][nrow];
        if (part != 0) {
            v.x = tf32r(v.x); v.y = tf32r(v.y);
            v.z = tf32r(v.z); v.w = tf32r(v.w);
        }
        float* dst = (part == 0) ? g_q : (part == 1) ? g_k : g_v;
        *(float4*)&dst[((size_t)(b * HEADS + head) * NN + n0 + nrow) * HD + dpos] = v;
    }
}

// =====================================================================
// Kernel 2: agent pooling — exact 8x8 block mean
// =====================================================================
__global__ void pool_kernel(const float* __restrict__ x) {
    int idx = blockIdx.x * 256 + threadIdx.x;
    if (idx >= BB * CC * AG) return;
    int a = idx % AG;
    int c = (idx / AG) % CC;
    int b = idx / (AG * CC);
    int ai = a / 7, aj = a % 7;
    const float* p = x + ((size_t)(b * CC + c) * HHW + ai * 8) * HHW + aj * 8;
    float s = 0.f;
#pragma unroll
    for (int r = 0; r < 8; r++) {
        float4 u = *(const float4*)&p[r * HHW];
        float4 u2 = *(const float4*)&p[r * HHW + 4];
        s += u.x + u.y + u.z + u.w + u2.x + u2.y + u2.z + u2.w;
    }
    s *= (1.0f / 64.0f);
    g_agent[((size_t)(b * HEADS + c / HD) * AG + a) * HD + (c % HD)] = s;
}

// =====================================================================
// Kernel 3: stage 1 — softmax over 49 agent tokens; output tf32-rounded
// and pre-scaled by SCALE (stage-2 logits).
// =====================================================================
__global__ __launch_bounds__(256) void stage1_kernel() {
    __shared__ float Ash[AG][HD];
    const int bh = blockIdx.y;
    const int n = blockIdx.x * 256 + threadIdx.x;

    {
        const float4* src = (const float4*)(g_agent + (size_t)bh * AG * HD);
        float4* dstp = (float4*)&Ash[0][0];
        for (int i = threadIdx.x; i < AG * HD / 4; i += 256) dstp[i] = src[i];
    }
    __syncthreads();
    if (n >= NN) return;

    float4 q[8];
    const float4* qp = (const float4*)(g_q + ((size_t)bh * NN + n) * HD);
#pragma unroll
    for (int i = 0; i < 8; i++) q[i] = qp[i];

    float l = 0.f;
    float4 qc[8];
#pragma unroll
    for (int i = 0; i < 8; i++) qc[i] = make_float4(0.f, 0.f, 0.f, 0.f);

#pragma unroll 7
    for (int a = 0; a < AG; a++) {
        const float4* ar = (const float4*)&Ash[a][0];
        float s = 0.f;
#pragma unroll
        for (int i = 0; i < 8; i++) {
            float4 av = ar[i];
            s += q[i].x * av.x + q[i].y * av.y + q[i].z * av.z + q[i].w * av.w;
        }
        float p = __expf(s * SCALE);  // logits tiny; no max needed
        l += p;
#pragma unroll
        for (int i = 0; i < 8; i++) {
            float4 av = ar[i];
            qc[i].x += p * av.x; qc[i].y += p * av.y;
            qc[i].z += p * av.z; qc[i].w += p * av.w;
        }
    }
    float inv = SCALE / l;
    float4* op = (float4*)(g_qc + ((size_t)bh * NN + n) * HD);
#pragma unroll
    for (int i = 0; i < 8; i++) {
        float4 v = qc[i];
        op[i] = make_float4(tf32r(v.x * inv), tf32r(v.y * inv),
                            tf32r(v.z * inv), tf32r(v.w * inv));
    }
}

// =====================================================================
// Kernel 4: stage 2 — tf32 mma flash attention, M=32 per warp,
// two 32-key halves, cp.async staging, uniform pad 36.
// P stored UNROUNDED (mma truncates on consume; l uses same raw p).
// =====================================================================
__global__ __launch_bounds__(64, 8) void flash_kernel() {
    __shared__ float Ksh[64][SP];
    __shared__ float Vsh[64][SP];
    __shared__ float Psh[2][32][SP];
    float (*Qsh)[SP] = (float(*)[SP])&Psh[0][0][0];  // 64x36 == 2x32x36

    const int bh = blockIdx.y;
    const int z = blockIdx.z;
    const int t = threadIdx.x;
    const int w = t >> 5;        // 0..1
    const int lane = t & 31;
    const int lr = lane >> 2;    // 0..7
    const int lc = lane & 3;     // 0..3
    const int nq0 = blockIdx.x * 64;

    // stage Q tile (64 x 32), coalesced
    {
        const float4* src = (const float4*)(g_qc + ((size_t)bh * NN + nq0) * HD);
#pragma unroll
        for (int i = t; i < 512; i += 64) {
            int r = i >> 3, c = i & 7;
            *(float4*)&Qsh[r][c * 4] = src[i];
        }
    }
    __syncthreads();

    // Q A-fragments: [mb][kc][reg]; warp rows w*32 + mb*16 + {lr, lr+8}
    unsigned qa[2][4][4];
#pragma unroll
    for (int mb = 0; mb < 2; mb++) {
        const int r0 = w * 32 + mb * 16;
#pragma unroll
        for (int kc = 0; kc < 4; kc++) {
            qa[mb][kc][0] = __float_as_uint(Qsh[r0 + lr][kc * 8 + lc]);
            qa[mb][kc][1] = __float_as_uint(Qsh[r0 + lr + 8][kc * 8 + lc]);
            qa[mb][kc][2] = __float_as_uint(Qsh[r0 + lr][kc * 8 + lc + 4]);
            qa[mb][kc][3] = __float_as_uint(Qsh[r0 + lr + 8][kc * 8 + lc + 4]);
        }
    }
    __syncthreads();  // Q reads done before Psh overlay is written

    float o[2][4][4];
#pragma unroll
    for (int mb = 0; mb < 2; mb++)
#pragma unroll
        for (int dc = 0; dc < 4; dc++)
#pragma unroll
            for (int i = 0; i < 4; i++) o[mb][dc][i] = 0.f;
    float la[2] = {0.f, 0.f}, lb[2] = {0.f, 0.f};

    const float* kbase = g_k + (size_t)bh * NN * HD;
    const float* vbase = g_v + (size_t)bh * NN * HD;

    const unsigned ksh0 = (unsigned)__cvta_generic_to_shared(&Ksh[0][0]);
    const unsigned vsh0 = (unsigned)__cvta_generic_to_shared(&Vsh[0][0]);

    const int tstart = (NTILES * z) / KSPLIT;
    const int tend = (NTILES * (z + 1)) / KSPLIT;

    for (int tt = tstart; tt < tend; tt++) {
        // stage K,V tiles (64 x 32 each) via cp.async
        {
            const float4* ks = (const float4*)(kbase + (size_t)tt * 64 * HD);
            const float4* vs = (const float4*)(vbase + (size_t)tt * 64 * HD);
#pragma unroll
            for (int i = t; i < 512; i += 64) {
                int r = i >> 3, c = i & 7;
                cp16(ksh0 + (r * SP + c * 4) * 4, ks + i);
                cp16(vsh0 + (r * SP + c * 4) * 4, vs + i);
            }
            asm volatile("cp.async.commit_group;\n");
            asm volatile("cp.async.wait_group 0;\n" ::: "memory");
        }
        __syncthreads();

#pragma unroll
        for (int kh = 0; kh < 2; kh++) {
            // S = Q K^T for 32-key half, exp, store P (raw fp32)
#pragma unroll
            for (int nc = 0; nc < 4; nc++) {
                const int krow = kh * 32 + nc * 8 + lr;
                float c0[2], c1[2], c2[2], c3[2];
#pragma unroll
                for (int mb = 0; mb < 2; mb++) { c0[mb] = c1[mb] = c2[mb] = c3[mb] = 0.f; }
#pragma unroll
                for (int kc = 0; kc < 4; kc++) {
                    unsigned b0 = __float_as_uint(Ksh[krow][kc * 8 + lc]);
                    unsigned b1 = __float_as_uint(Ksh[krow][kc * 8 + lc + 4]);
                    mma8(c0[0], c1[0], c2[0], c3[0],
                         qa[0][kc][0], qa[0][kc][1], qa[0][kc][2], qa[0][kc][3], b0, b1);
                    mma8(c0[1], c1[1], c2[1], c3[1],
                         qa[1][kc][0], qa[1][kc][1], qa[1][kc][2], qa[1][kc][3], b0, b1);
                }
#pragma unroll
                for (int mb = 0; mb < 2; mb++) {
                    float p0 = __expf(c0[mb]);
                    float p1 = __expf(c1[mb]);
                    float p2 = __expf(c2[mb]);
                    float p3 = __expf(c3[mb]);
                    la[mb] += p0 + p1;   // row mb*16+lr
                    lb[mb] += p2 + p3;   // row mb*16+lr+8
                    *(float2*)&Psh[w][mb * 16 + lr][nc * 8 + 2 * lc] = make_float2(p0, p1);
                    *(float2*)&Psh[w][mb * 16 + lr + 8][nc * 8 + 2 * lc] = make_float2(p2, p3);
                }
            }
            __syncwarp();

            // O += P V for this half (both row-blocks share V B-frags)
#pragma unroll
            for (int kc = 0; kc < 4; kc++) {
                unsigned a[2][4];
#pragma unroll
                for (int mb = 0; mb < 2; mb++) {
                    a[mb][0] = __float_as_uint(Psh[w][mb * 16 + lr][kc * 8 + lc]);
                    a[mb][1] = __float_as_uint(Psh[w][mb * 16 + lr + 8][kc * 8 + lc]);
                    a[mb][2] = __float_as_uint(Psh[w][mb * 16 + lr][kc * 8 + lc + 4]);
                    a[mb][3] = __float_as_uint(Psh[w][mb * 16 + lr + 8][kc * 8 + lc + 4]);
                }
                const int vrow = kh * 32 + kc * 8;
#pragma unroll
                for (int dc = 0; dc < 4; dc++) {
                    unsigned b0 = __float_as_uint(Vsh[vrow + lc][dc * 8 + lr]);
                    unsigned b1 = __float_as_uint(Vsh[vrow + lc + 4][dc * 8 + lr]);
                    mma8(o[0][dc][0], o[0][dc][1], o[0][dc][2], o[0][dc][3],
                         a[0][0], a[0][1], a[0][2], a[0][3], b0, b1);
                    mma8(o[1][dc][0], o[1][dc][1], o[1][dc][2], o[1][dc][3],
                         a[1][0], a[1][1], a[1][2], a[1][3], b0, b1);
                }
            }
            __syncwarp();  // Psh reads done before next half overwrites
        }
        __syncthreads();   // K/V reads done before next tile staging
    }

    // epilogue: reduce l over the quad owning each row, write partials
#pragma unroll
    for (int mb = 0; mb < 2; mb++) {
        la[mb] += __shfl_xor_sync(0xFFFFFFFFu, la[mb], 1);
        la[mb] += __shfl_xor_sync(0xFFFFFFFFu, la[mb], 2);
        lb[mb] += __shfl_xor_sync(0xFFFFFFFFu, lb[mb], 1);
        lb[mb] += __shfl_xor_sync(0xFFFFFFFFu, lb[mb], 2);
    }

    const size_t prow = ((size_t)z * BB * HEADS + bh) * NN + nq0 + w * 32;
#pragma unroll
    for (int mb = 0; mb < 2; mb++) {
        const size_t r0 = prow + mb * 16;
        if (lc == 0) {
            g_pl[r0 + lr] = la[mb];
            g_pl[r0 + lr + 8] = lb[mb];
        }
#pragma unroll
        for (int dc = 0; dc < 4; dc++) {
            *(float2*)&g_po[(r0 + lr) * HD + dc * 8 + 2 * lc] =
                make_float2(o[mb][dc][0], o[mb][dc][1]);
            *(float2*)&g_po[(r0 + lr + 8) * HD + dc * 8 + 2 * lc] =
                make_float2(o[mb][dc][2], o[mb][dc][3]);
        }
    }
}

// =====================================================================
// Kernel 4b: combine split-K partials -> ctx [b, n, c]
// =====================================================================
__global__ __launch_bounds__(256) void combine_kernel() {
    const int idx = blockIdx.x * 256 + threadIdx.x;  // over bh*NN
    if (idx >= BB * HEADS * NN) return;
    const int bh = idx / NN;
    const int n = idx % NN;

    float L = 0.f;
    float4 acc[8];
#pragma unroll
    for (int i = 0; i < 8; i++) acc[i] = make_float4(0.f, 0.f, 0.f, 0.f);
#pragma unroll
    for (int z = 0; z < KSPLIT; z++) {
        const size_t pidx = ((size_t)z * BB * HEADS + bh) * NN + n;
        L += g_pl[pidx];
        const float4* op = (const float4*)(g_po + pidx * HD);
#pragma unroll
        for (int i = 0; i < 8; i++) {
            float4 v = op[i];
            acc[i].x += v.x; acc[i].y += v.y;
            acc[i].z += v.z; acc[i].w += v.w;
        }
    }
    float inv = 1.f / L;
    const int b = bh / HEADS, h = bh % HEADS;
    float4* dst = (float4*)(g_ctx + ((size_t)b * NN + n) * CC + h * HD);
#pragma unroll
    for (int i = 0; i < 8; i++) {
        float4 v = acc[i];
        dst[i] = make_float4(v.x * inv, v.y * inv, v.z * inv, v.w * inv);
    }
}

// =====================================================================
// Kernel 5: proj GEMM via tf32 mma (2-term: Ch*Wh + Ch*Wl; ctx rna-rounded
// at staging) + bias + LayerNorm + transpose to [b,c,n].
// CTA: 128 thr (4 warps), tile 64n x 128o (full o-width -> LN in-CTA).
// W staged [o][c] (no transpose) -> B-frag bank = 4*lr+lc, conflict-free.
// =====================================================================
__global__ __launch_bounds__(128) void proj_ln_kernel(const float* __restrict__ wp,
                                                      const float* __restrict__ bp,
                                                      const float* __restrict__ lg,
                                                      const float* __restrict__ lb,
                                                      float* __restrict__ out) {
    __shared__ float SB[64 * 36 + 128 * 36 * 2];  // 46080 B
    float (*Csh)[36] = (float(*)[36])SB;                 // ctx tile (tf32)
    float (*Whh)[36] = (float(*)[36])(SB + 64 * 36);     // W hi
    float (*Whl)[36] = (float(*)[36])(SB + 64 * 36 + 128 * 36);  // W lo
    float (*Osh)[PO] = (float(*)[PO])SB;                 // overlay, 64 x 133
    __shared__ float mu_s[64], rs_s[64];

    const int b = blockIdx.y;
    const int n0 = blockIdx.x * 64;
    const int t = threadIdx.x;
    const int wid = t >> 5;
    const int lane = t & 31;
    const int lr = lane >> 2;
    const int lc = lane & 3;
    const int wn = (wid & 1) * 32;   // warp n offset
    const int wo = (wid >> 1) * 64;  // warp o offset

    float c[2][8][4];
#pragma unroll
    for (int mb = 0; mb < 2; mb++)
#pragma unroll
        for (int nc = 0; nc < 8; nc++)
#pragma unroll
            for (int i = 0; i < 4; i++) c[mb][nc][i] = 0.f;

    const float* ctx = g_ctx + ((size_t)b * NN + n0) * CC;

    for (int c0 = 0; c0 < CC; c0 += 32) {
        // stage ctx 64n x 32c, tf32-rounded
#pragma unroll
        for (int i = t; i < 512; i += 128) {
            int row = i >> 3, cq = (i & 7) * 4;
            float4 v = *(const float4*)&ctx[(size_t)row * CC + c0 + cq];
            *(float4*)&Csh[row][cq] = make_float4(tf32r(v.x), tf32r(v.y),
                                                  tf32r(v.z), tf32r(v.w));
        }
        // stage W 128o x 32c hi/lo, [o][c] layout (no transpose)
#pragma unroll
        for (int i = t; i < 1024; i += 128) {
            int row = i >> 3, cq = (i & 7) * 4;
            float4 v = *(const float4*)&wp[(size_t)row * CC + c0 + cq];
            float4 h = make_float4(tf32r(v.x), tf32r(v.y), tf32r(v.z), tf32r(v.w));
            float4 l = make_float4(tf32r(v.x - h.x), tf32r(v.y - h.y),
                                   tf32r(v.z - h.z), tf32r(v.w - h.w));
            *(float4*)&Whh[row][cq] = h;
            *(float4*)&Whl[row][cq] = l;
        }
        __syncthreads();

#pragma unroll
        for (int kc = 0; kc < 4; kc++) {
            unsigned a[2][4];
#pragma unroll
            for (int mb = 0; mb < 2; mb++) {
                const int r0 = wn + mb * 16;
                a[mb][0] = __float_as_uint(Csh[r0 + lr][kc * 8 + lc]);
                a[mb][1] = __float_as_uint(Csh[r0 + lr + 8][kc * 8 + lc]);
                a[mb][2] = __float_as_uint(Csh[r0 + lr][kc * 8 + lc + 4]);
                a[mb][3] = __float_as_uint(Csh[r0 + lr + 8][kc * 8 + lc + 4]);
            }
#pragma unroll
            for (int nc = 0; nc < 8; nc++) {
                const int orow = wo + nc * 8 + lr;
                unsigned bh0 = __float_as_uint(Whh[orow][kc * 8 + lc]);
                unsigned bh1 = __float_as_uint(Whh[orow][kc * 8 + lc + 4]);
                unsigned bl0 = __float_as_uint(Whl[orow][kc * 8 + lc]);
                unsigned bl1 = __float_as_uint(Whl[orow][kc * 8 + lc + 4]);
#pragma unroll
                for (int mb = 0; mb < 2; mb++) {
                    mma8(c[mb][nc][0], c[mb][nc][1], c[mb][nc][2], c[mb][nc][3],
                         a[mb][0], a[mb][1], a[mb][2], a[mb][3], bh0, bh1);
                    mma8(c[mb][nc][0], c[mb][nc][1], c[mb][nc][2], c[mb][nc][3],
                         a[mb][0], a[mb][1], a[mb][2], a[mb][3], bl0, bl1);
                }
            }
        }
        __syncthreads();
    }

    // frags -> Osh[n][o] (+bias). mma B n-index = o; C cols are o.
#pragma unroll
    for (int mb = 0; mb < 2; mb++) {
        const int r0 = wn + mb * 16;
#pragma unroll
        for (int nc = 0; nc < 8; nc++) {
            const int oc = wo + nc * 8 + 2 * lc;
            float b0 = bp[oc], b1 = bp[oc + 1];
            Osh[r0 + lr][oc] = c[mb][nc][0] + b0;
            Osh[r0 + lr][oc + 1] = c[mb][nc][1] + b1;
            Osh[r0 + lr + 8][oc] = c[mb][nc][2] + b0;
            Osh[r0 + lr + 8][oc + 1] = c[mb][nc][3] + b1;
        }
    }
    __syncthreads();

    // LayerNorm stats: warp w handles rows 16w..16w+15
    {
        for (int r = wid * 16; r < wid * 16 + 16; r++) {
            float sv = 0.f, sq = 0.f;
#pragma unroll
            for (int oq = 0; oq < 4; oq++) {
                float v = Osh[r][lane + 32 * oq];
                sv += v; sq += v * v;
            }
#pragma unroll
            for (int off = 16; off; off >>= 1) {
                sv += __shfl_xor_sync(0xFFFFFFFFu, sv, off);
                sq += __shfl_xor_sync(0xFFFFFFFFu, sq, off);
            }
            if (lane == 0) {
                float mu = sv * (1.f / 128.f);
                float var = sq * (1.f / 128.f) - mu * mu;
                mu_s[r] = mu;
                rs_s[r] = rsqrtf(var + LN_EPS);
            }
        }
    }
    __syncthreads();

    // normalize + transpose write: coalesced over n (64-wide rows)
#pragma unroll
    for (int i = 0; i < 64; i++) {
        int e = t + 128 * i;
        int o = e >> 6, nl = e & 63;
        float v = (Osh[nl][o] - mu_s[nl]) * rs_s[nl] * lg[o] + lb[o];
        out[(size_t)(b * CC + o) * NN + n0 + nl] = v;
    }
}

// =====================================================================
extern "C" void kernel_launch(void* const* d_in, const int* in_sizes, int n_in,
                              void* d_out, int out_size) {
    const float* x      = (const float*)d_in[0];
    const float* w_qkv  = (const float*)d_in[1];
    const float* w_proj = (const float*)d_in[2];
    const float* b_proj = (const float*)d_in[3];
    const float* ln_g   = (const float*)d_in[4];
    const float* ln_b   = (const float*)d_in[5];
    float* out = (float*)d_out;

    dim3 g1(NN / 64, 384 / 64, BB);
    qkv_kernel<<<g1, 128>>>(x, w_qkv);

    pool_kernel<<<(BB * CC * AG + 255) / 256, 256>>>(x);

    dim3 g3((NN + 255) / 256, BB * HEADS);
    stage1_kernel<<<g3, 256>>>();

    dim3 g4(NN / 64, BB * HEADS, KSPLIT);
    flash_kernel<<<g4, 64>>>();

    combine_kernel<<<(BB * HEADS * NN + 255) / 256, 256>>>();

    dim3 g5(NN / 64, BB);
    proj_ln_kernel<<<g5, 128>>>(w_proj, b_proj, ln_g, ln_b, out);
}

// round 15
// speedup vs baseline: 1.6468x; 1.2928x over previous
#include <cuda_runtime.h>
#include <cuda_fp16.h>
#include <cstdint>

#define BB 2
#define CC 128
#define HHW 56
#define NN 3136
#define HEADS 4
#define HD 32
#define AG 49
#define SCALE 0.1767766952966369f  // 32^-0.5
#define LN_EPS 1e-5f
#define KSPLIT 7
#define NTILES 49          // NN / 64

#define SP 36  // uniform smem pad (floats): conflict-free K/Q frag accesses
#define PO 133 // proj LN epilogue pad: gcd(5,32)=1 -> conflict-free column reads

// ---------------- scratch (device globals; no allocation allowed) ----------------
__device__ float g_q[BB * HEADS * NN * HD];
__device__ float g_k[BB * HEADS * NN * HD];            // tf32-rounded
__device__ __half2 g_vh2[BB * HEADS * HD * NN / 2];    // V fp16, [bh][d][key] pairs
__device__ float g_agent[BB * HEADS * AG * HD];
__device__ float g_qc[BB * HEADS * NN * HD];           // tf32-rounded, pre-scaled
__device__ float g_ctx[BB * NN * CC];
// split-K partials (no max needed: logits are tiny, exp(s) directly)
__device__ float g_po[KSPLIT * BB * HEADS * NN * HD];
__device__ float g_pl[KSPLIT * BB * HEADS * NN];

// ---------------- helpers ----------------
__device__ __forceinline__ float tf32r(float x) {
    asm("cvt.rna.tf32.f32 %0, %0;" : "+f"(x));
    return x;
}

__device__ __forceinline__ void mma8(float& c0, float& c1, float& c2, float& c3,
                                     unsigned a0, unsigned a1, unsigned a2, unsigned a3,
                                     unsigned b0, unsigned b1) {
    asm("mma.sync.aligned.m16n8k8.row.col.f32.tf32.tf32.f32 "
        "{%0,%1,%2,%3}, {%4,%5,%6,%7}, {%8,%9}, {%0,%1,%2,%3};"
        : "+f"(c0), "+f"(c1), "+f"(c2), "+f"(c3)
        : "r"(a0), "r"(a1), "r"(a2), "r"(a3), "r"(b0), "r"(b1));
}

__device__ __forceinline__ void mma16h(float& c0, float& c1, float& c2, float& c3,
                                       unsigned a0, unsigned a1, unsigned a2, unsigned a3,
                                       unsigned b0, unsigned b1) {
    asm("mma.sync.aligned.m16n8k16.row.col.f32.f16.f16.f32 "
        "{%0,%1,%2,%3}, {%4,%5,%6,%7}, {%8,%9}, {%0,%1,%2,%3};"
        : "+f"(c0), "+f"(c1), "+f"(c2), "+f"(c3)
        : "r"(a0), "r"(a1), "r"(a2), "r"(a3), "r"(b0), "r"(b1));
}

__device__ __forceinline__ void cp16(unsigned smem_addr, const void* gptr) {
    asm volatile("cp.async.ca.shared.global [%0], [%1], 16;\n"
                 :: "r"(smem_addr), "l"(gptr));
}

__device__ __forceinline__ unsigned packh2(float a, float b) {
    __half2 h = __floats2half2_rn(a, b);
    return *(unsigned*)&h;
}

// =====================================================================
// Kernel 1: QKV 1x1 conv via 3xTF32 tensor-core GEMM.
// V written as fp16 TRANSPOSED [bh][d][key] (for flash PV B-frags).
// =====================================================================
__global__ __launch_bounds__(128) void qkv_kernel(const float* __restrict__ x,
                                                  const float* __restrict__ w) {
    __shared__ float SB[64 * 36 * 2 + 32 * 68 * 2];  // 35840 B
    float (*Whi)[36] = (float(*)[36])SB;
    float (*Wlo)[36] = (float(*)[36])(SB + 64 * 36);
    float (*Xhi)[68] = (float(*)[68])(SB + 64 * 36 * 2);
    float (*Xlo)[68] = (float(*)[68])(SB + 64 * 36 * 2 + 32 * 68);
    float (*Osh)[68] = (float(*)[68])SB;  // overlay (after k-loop)

    const int b = blockIdx.z;
    const int o0 = blockIdx.y * 64;
    const int n0 = blockIdx.x * 64;
    const int t = threadIdx.x;
    const int wid = t >> 5;
    const int lane = t & 31;
    const int lr = lane >> 2;
    const int lc = lane & 3;
    const int wo2 = (wid >> 1) * 32;
    const int wn2 = (wid & 1) * 32;

    float c[2][4][4];
#pragma unroll
    for (int mb = 0; mb < 2; mb++)
#pragma unroll
        for (int nc = 0; nc < 4; nc++)
#pragma unroll
            for (int i = 0; i < 4; i++) c[mb][nc][i] = 0.f;

    const float* xb = x + (size_t)b * CC * NN;

    for (int k0 = 0; k0 < CC; k0 += 32) {
        {
            int wrow = t >> 3, wcol = (t & 7) * 4;
#pragma unroll
            for (int u = 0; u < 4; u++) {
                int wo = wrow + u * 16;
                float4 v = *(const float4*)&w[(size_t)(o0 + wo) * CC + k0 + wcol];
                float4 h = make_float4(tf32r(v.x), tf32r(v.y), tf32r(v.z), tf32r(v.w));
                float4 l = make_float4(tf32r(v.x - h.x), tf32r(v.y - h.y),
                                       tf32r(v.z - h.z), tf32r(v.w - h.w));
                *(float4*)&Whi[wo][wcol] = h;
                *(float4*)&Wlo[wo][wcol] = l;
            }
        }
        {
            int xrow = t >> 4, xcol = (t & 15) * 4;
#pragma unroll
            for (int u = 0; u < 4; u++) {
                int xc = xrow + u * 8;
                float4 v = *(const float4*)&xb[(size_t)(k0 + xc) * NN + n0 + xcol];
                float4 h = make_float4(tf32r(v.x), tf32r(v.y), tf32r(v.z), tf32r(v.w));
                float4 l = make_float4(tf32r(v.x - h.x), tf32r(v.y - h.y),
                                       tf32r(v.z - h.z), tf32r(v.w - h.w));
                *(float4*)&Xhi[xc][xcol] = h;
                *(float4*)&Xlo[xc][xcol] = l;
            }
        }
        __syncthreads();

#pragma unroll
        for (int kc = 0; kc < 4; kc++) {
            unsigned ah[2][4], al[2][4];
#pragma unroll
            for (int mb = 0; mb < 2; mb++) {
                const int r0 = wo2 + mb * 16;
                ah[mb][0] = __float_as_uint(Whi[r0 + lr][kc * 8 + lc]);
                ah[mb][1] = __float_as_uint(Whi[r0 + lr + 8][kc * 8 + lc]);
                ah[mb][2] = __float_as_uint(Whi[r0 + lr][kc * 8 + lc + 4]);
                ah[mb][3] = __float_as_uint(Whi[r0 + lr + 8][kc * 8 + lc + 4]);
                al[mb][0] = __float_as_uint(Wlo[r0 + lr][kc * 8 + lc]);
                al[mb][1] = __float_as_uint(Wlo[r0 + lr + 8][kc * 8 + lc]);
                al[mb][2] = __float_as_uint(Wlo[r0 + lr][kc * 8 + lc + 4]);
                al[mb][3] = __float_as_uint(Wlo[r0 + lr + 8][kc * 8 + lc + 4]);
            }
#pragma unroll
            for (int nc = 0; nc < 4; nc++) {
                unsigned bh0 = __float_as_uint(Xhi[kc * 8 + lc][wn2 + nc * 8 + lr]);
                unsigned bh1 = __float_as_uint(Xhi[kc * 8 + lc + 4][wn2 + nc * 8 + lr]);
                unsigned bl0 = __float_as_uint(Xlo[kc * 8 + lc][wn2 + nc * 8 + lr]);
                unsigned bl1 = __float_as_uint(Xlo[kc * 8 + lc + 4][wn2 + nc * 8 + lr]);
#pragma unroll
                for (int mb = 0; mb < 2; mb++) {
                    mma8(c[mb][nc][0], c[mb][nc][1], c[mb][nc][2], c[mb][nc][3],
                         ah[mb][0], ah[mb][1], ah[mb][2], ah[mb][3], bh0, bh1);
                    mma8(c[mb][nc][0], c[mb][nc][1], c[mb][nc][2], c[mb][nc][3],
                         ah[mb][0], ah[mb][1], ah[mb][2], ah[mb][3], bl0, bl1);
                    mma8(c[mb][nc][0], c[mb][nc][1], c[mb][nc][2], c[mb][nc][3],
                         al[mb][0], al[mb][1], al[mb][2], al[mb][3], bh0, bh1);
                }
            }
        }
        __syncthreads();
    }

#pragma unroll
    for (int mb = 0; mb < 2; mb++) {
        const int r0 = wo2 + mb * 16;
#pragma unroll
        for (int nc = 0; nc < 4; nc++) {
            *(float2*)&Osh[r0 + lr][wn2 + nc * 8 + 2 * lc] =
                make_float2(c[mb][nc][0], c[mb][nc][1]);
            *(float2*)&Osh[r0 + lr + 8][wn2 + nc * 8 + 2 * lc] =
                make_float2(c[mb][nc][2], c[mb][nc][3]);
        }
    }
    __syncthreads();

    const int part_blk = o0 >> 7;  // 0=q 1=k 2=v (each 64-o block within one part)
    if (part_blk == 2) {
        // V: fp16 transposed writeout [bh][d][key], half2 pairs along key
#pragma unroll
        for (int i = 0; i < 16; i++) {
            int idx = t + 128 * i;       // 0..2047
            int row = idx >> 5;          // o row 0..63
            int pr = idx & 31;           // key pair 0..31
            int og = o0 + row;
            int head = (og >> 5) & 3;
            int d = og & 31;
            float2 v2 = *(float2*)&Osh[row][2 * pr];
            g_vh2[((size_t)(b * HEADS + head) * HD + d) * (NN / 2) + (n0 >> 1) + pr] =
                __floats2half2_rn(v2.x, v2.y);
        }
    } else {
#pragma unroll
        for (int p = 0; p < 8; p++) {
            const int oh = p & 1;
            const int ng = p >> 1;
            const int nrow = ng * 16 + (t >> 3);
            const int dpos = (t & 7) * 4;
            const int og = o0 + oh * 32;
            const int head = (og >> 5) & 3;
            float4 v;
            v.x = Osh[oh * 32 + dpos + 0][nrow];
            v.y = Osh[oh * 32 + dpos + 1][nrow];
            v.z = Osh[oh * 32 + dpos + 2][nrow];
            v.w = Osh[oh * 32 + dpos + 3][nrow];
            if (part_blk == 1) {
                v.x = tf32r(v.x); v.y = tf32r(v.y);
                v.z = tf32r(v.z); v.w = tf32r(v.w);
            }
            float* dst = (part_blk == 0) ? g_q : g_k;
            *(float4*)&dst[((size_t)(b * HEADS + head) * NN + n0 + nrow) * HD + dpos] = v;
        }
    }
}

// =====================================================================
// Kernel 2: agent pooling — exact 8x8 block mean
// =====================================================================
__global__ void pool_kernel(const float* __restrict__ x) {
    int idx = blockIdx.x * 256 + threadIdx.x;
    if (idx >= BB * CC * AG) return;
    int a = idx % AG;
    int c = (idx / AG) % CC;
    int b = idx / (AG * CC);
    int ai = a / 7, aj = a % 7;
    const float* p = x + ((size_t)(b * CC + c) * HHW + ai * 8) * HHW + aj * 8;
    float s = 0.f;
#pragma unroll
    for (int r = 0; r < 8; r++) {
        float4 u = *(const float4*)&p[r * HHW];
        float4 u2 = *(const float4*)&p[r * HHW + 4];
        s += u.x + u.y + u.z + u.w + u2.x + u2.y + u2.z + u2.w;
    }
    s *= (1.0f / 64.0f);
    g_agent[((size_t)(b * HEADS + c / HD) * AG + a) * HD + (c % HD)] = s;
}

// =====================================================================
// Kernel 3: stage 1 — softmax over 49 agent tokens; output tf32-rounded
// and pre-scaled by SCALE (stage-2 logits).
// =====================================================================
__global__ __launch_bounds__(256) void stage1_kernel() {
    __shared__ float Ash[AG][HD];
    const int bh = blockIdx.y;
    const int n = blockIdx.x * 256 + threadIdx.x;

    {
        const float4* src = (const float4*)(g_agent + (size_t)bh * AG * HD);
        float4* dstp = (float4*)&Ash[0][0];
        for (int i = threadIdx.x; i < AG * HD / 4; i += 256) dstp[i] = src[i];
    }
    __syncthreads();
    if (n >= NN) return;

    float4 q[8];
    const float4* qp = (const float4*)(g_q + ((size_t)bh * NN + n) * HD);
#pragma unroll
    for (int i = 0; i < 8; i++) q[i] = qp[i];

    float l = 0.f;
    float4 qc[8];
#pragma unroll
    for (int i = 0; i < 8; i++) qc[i] = make_float4(0.f, 0.f, 0.f, 0.f);

#pragma unroll 7
    for (int a = 0; a < AG; a++) {
        const float4* ar = (const float4*)&Ash[a][0];
        float s = 0.f;
#pragma unroll
        for (int i = 0; i < 8; i++) {
            float4 av = ar[i];
            s += q[i].x * av.x + q[i].y * av.y + q[i].z * av.z + q[i].w * av.w;
        }
        float p = __expf(s * SCALE);  // logits tiny; no max needed
        l += p;
#pragma unroll
        for (int i = 0; i < 8; i++) {
            float4 av = ar[i];
            qc[i].x += p * av.x; qc[i].y += p * av.y;
            qc[i].z += p * av.z; qc[i].w += p * av.w;
        }
    }
    float inv = SCALE / l;
    float4* op = (float4*)(g_qc + ((size_t)bh * NN + n) * HD);
#pragma unroll
    for (int i = 0; i < 8; i++) {
        float4 v = qc[i];
        op[i] = make_float4(tf32r(v.x * inv), tf32r(v.y * inv),
                            tf32r(v.z * inv), tf32r(v.w * inv));
    }
}

// =====================================================================
// Kernel 4: stage 2 — flash attention. S via tf32 mma; P stays in
// REGISTERS: S C-frags of two adjacent n8 blocks pack directly into the
// fp16 A-frag of mma.m16n8k16 (FA2 trick; fp16 == tf32 mantissa, so no
// extra error). PV via fp16 mma with V staged as half2 [d][key].
// No Psh, no inner syncs. smem 22.5KB, 8 CTAs/SM target.
// =====================================================================
__global__ __launch_bounds__(64, 8) void flash_kernel() {
    __shared__ float Qsh[64][SP];
    __shared__ float Ksh[64][SP];
    __shared__ __align__(16) __half2 Vsh[32][36];  // [d][key-pair], bank 4d+pr

    const int bh = blockIdx.y;
    const int z = blockIdx.z;
    const int t = threadIdx.x;
    const int w = t >> 5;
    const int lane = t & 31;
    const int lr = lane >> 2;
    const int lc = lane & 3;
    const int nq0 = blockIdx.x * 64;

    // stage Q tile (64 x 32), coalesced
    {
        const float4* src = (const float4*)(g_qc + ((size_t)bh * NN + nq0) * HD);
#pragma unroll
        for (int i = t; i < 512; i += 64) {
            int r = i >> 3, c = i & 7;
            *(float4*)&Qsh[r][c * 4] = src[i];
        }
    }
    __syncthreads();

    // Q A-fragments: [mb][kc][reg]; warp rows w*32 + mb*16 + {lr, lr+8}
    unsigned qa[2][4][4];
#pragma unroll
    for (int mb = 0; mb < 2; mb++) {
        const int r0 = w * 32 + mb * 16;
#pragma unroll
        for (int kc = 0; kc < 4; kc++) {
            qa[mb][kc][0] = __float_as_uint(Qsh[r0 + lr][kc * 8 + lc]);
            qa[mb][kc][1] = __float_as_uint(Qsh[r0 + lr + 8][kc * 8 + lc]);
            qa[mb][kc][2] = __float_as_uint(Qsh[r0 + lr][kc * 8 + lc + 4]);
            qa[mb][kc][3] = __float_as_uint(Qsh[r0 + lr + 8][kc * 8 + lc + 4]);
        }
    }

    float o[2][4][4];
#pragma unroll
    for (int mb = 0; mb < 2; mb++)
#pragma unroll
        for (int dc = 0; dc < 4; dc++)
#pragma unroll
            for (int i = 0; i < 4; i++) o[mb][dc][i] = 0.f;
    float la[2] = {0.f, 0.f}, lb[2] = {0.f, 0.f};

    const float* kbase = g_k + (size_t)bh * NN * HD;
    const __half2* vbase = g_vh2 + (size_t)bh * HD * (NN / 2);

    const unsigned ksh0 = (unsigned)__cvta_generic_to_shared(&Ksh[0][0]);
    const unsigned vsh0 = (unsigned)__cvta_generic_to_shared(&Vsh[0][0]);

    const int tstart = (NTILES * z) / KSPLIT;
    const int tend = (NTILES * (z + 1)) / KSPLIT;

    for (int tt = tstart; tt < tend; tt++) {
        // stage K (64x32 fp32) + V (32d x 64key fp16) via cp.async
        {
            const float4* ks = (const float4*)(kbase + (size_t)tt * 64 * HD);
#pragma unroll
            for (int i = t; i < 512; i += 64) {
                int r = i >> 3, c = i & 7;
                cp16(ksh0 + (r * SP + c * 4) * 4, ks + i);
            }
#pragma unroll
            for (int i = t; i < 256; i += 64) {
                int d = i >> 3, ch = i & 7;
                cp16(vsh0 + d * 144 + ch * 16,
                     vbase + (size_t)d * (NN / 2) + tt * 32 + ch * 4);
            }
            asm volatile("cp.async.commit_group;\n");
            asm volatile("cp.async.wait_group 0;\n" ::: "memory");
        }
        __syncthreads();

        // process 16-key groups: S (tf32) -> exp -> reg-pack -> PV (fp16)
#pragma unroll
        for (int g = 0; g < 4; g++) {
            float s[2][2][4];  // [blk][mb][reg]
#pragma unroll
            for (int blk = 0; blk < 2; blk++) {
                const int krow = (2 * g + blk) * 8 + lr;
#pragma unroll
                for (int mb = 0; mb < 2; mb++)
#pragma unroll
                    for (int i = 0; i < 4; i++) s[blk][mb][i] = 0.f;
#pragma unroll
                for (int kc = 0; kc < 4; kc++) {
                    unsigned b0 = __float_as_uint(Ksh[krow][kc * 8 + lc]);
                    unsigned b1 = __float_as_uint(Ksh[krow][kc * 8 + lc + 4]);
                    mma8(s[blk][0][0], s[blk][0][1], s[blk][0][2], s[blk][0][3],
                         qa[0][kc][0], qa[0][kc][1], qa[0][kc][2], qa[0][kc][3], b0, b1);
                    mma8(s[blk][1][0], s[blk][1][1], s[blk][1][2], s[blk][1][3],
                         qa[1][kc][0], qa[1][kc][1], qa[1][kc][2], qa[1][kc][3], b0, b1);
                }
            }
            unsigned pa[2][4];
#pragma unroll
            for (int mb = 0; mb < 2; mb++) {
                float p00 = __expf(s[0][mb][0]);
                float p01 = __expf(s[0][mb][1]);
                float p02 = __expf(s[0][mb][2]);
                float p03 = __expf(s[0][mb][3]);
                float p10 = __expf(s[1][mb][0]);
                float p11 = __expf(s[1][mb][1]);
                float p12 = __expf(s[1][mb][2]);
                float p13 = __expf(s[1][mb][3]);
                la[mb] += p00 + p01 + p10 + p11;  // row mb*16+lr
                lb[mb] += p02 + p03 + p12 + p13;  // row mb*16+lr+8
                pa[mb][0] = packh2(p00, p01);  // A[lr][2lc,2lc+1]      (k 16g+)
                pa[mb][1] = packh2(p02, p03);  // A[lr+8][2lc,2lc+1]
                pa[mb][2] = packh2(p10, p11);  // A[lr][2lc+8,2lc+9]
                pa[mb][3] = packh2(p12, p13);  // A[lr+8][2lc+8,2lc+9]
            }
#pragma unroll
            for (int dc = 0; dc < 4; dc++) {
                unsigned b0 = *(const unsigned*)&Vsh[dc * 8 + lr][8 * g + lc];
                unsigned b1 = *(const unsigned*)&Vsh[dc * 8 + lr][8 * g + lc + 4];
                mma16h(o[0][dc][0], o[0][dc][1], o[0][dc][2], o[0][dc][3],
                       pa[0][0], pa[0][1], pa[0][2], pa[0][3], b0, b1);
                mma16h(o[1][dc][0], o[1][dc][1], o[1][dc][2], o[1][dc][3],
                       pa[1][0], pa[1][1], pa[1][2], pa[1][3], b0, b1);
            }
        }
        __syncthreads();  // K/V reads done before next tile staging
    }

    // epilogue: reduce l over the quad owning each row, write partials
#pragma unroll
    for (int mb = 0; mb < 2; mb++) {
        la[mb] += __shfl_xor_sync(0xFFFFFFFFu, la[mb], 1);
        la[mb] += __shfl_xor_sync(0xFFFFFFFFu, la[mb], 2);
        lb[mb] += __shfl_xor_sync(0xFFFFFFFFu, lb[mb], 1);
        lb[mb] += __shfl_xor_sync(0xFFFFFFFFu, lb[mb], 2);
    }

    const size_t prow = ((size_t)z * BB * HEADS + bh) * NN + nq0 + w * 32;
#pragma unroll
    for (int mb = 0; mb < 2; mb++) {
        const size_t r0 = prow + mb * 16;
        if (lc == 0) {
            g_pl[r0 + lr] = la[mb];
            g_pl[r0 + lr + 8] = lb[mb];
        }
#pragma unroll
        for (int dc = 0; dc < 4; dc++) {
            *(float2*)&g_po[(r0 + lr) * HD + dc * 8 + 2 * lc] =
                make_float2(o[mb][dc][0], o[mb][dc][1]);
            *(float2*)&g_po[(r0 + lr + 8) * HD + dc * 8 + 2 * lc] =
                make_float2(o[mb][dc][2], o[mb][dc][3]);
        }
    }
}

// =====================================================================
// Kernel 4b: combine split-K partials -> ctx [b, n, c]
// =====================================================================
__global__ __launch_bounds__(256) void combine_kernel() {
    const int idx = blockIdx.x * 256 + threadIdx.x;  // over bh*NN
    if (idx >= BB * HEADS * NN) return;
    const int bh = idx / NN;
    const int n = idx % NN;

    float L = 0.f;
    float4 acc[8];
#pragma unroll
    for (int i = 0; i < 8; i++) acc[i] = make_float4(0.f, 0.f, 0.f, 0.f);
#pragma unroll
    for (int z = 0; z < KSPLIT; z++) {
        const size_t pidx = ((size_t)z * BB * HEADS + bh) * NN + n;
        L += g_pl[pidx];
        const float4* op = (const float4*)(g_po + pidx * HD);
#pragma unroll
        for (int i = 0; i < 8; i++) {
            float4 v = op[i];
            acc[i].x += v.x; acc[i].y += v.y;
            acc[i].z += v.z; acc[i].w += v.w;
        }
    }
    float inv = 1.f / L;
    const int b = bh / HEADS, h = bh % HEADS;
    float4* dst = (float4*)(g_ctx + ((size_t)b * NN + n) * CC + h * HD);
#pragma unroll
    for (int i = 0; i < 8; i++) {
        float4 v = acc[i];
        dst[i] = make_float4(v.x * inv, v.y * inv, v.z * inv, v.w * inv);
    }
}

// =====================================================================
// Kernel 5: proj GEMM via 3-term tf32 mma (Ch*Wh + Ch*Wl + Cl*Wh)
// + bias + LayerNorm + transpose to [b,c,n].
// =====================================================================
__global__ __launch_bounds__(128) void proj_ln_kernel(const float* __restrict__ wp,
                                                      const float* __restrict__ bp,
                                                      const float* __restrict__ lg,
                                                      const float* __restrict__ lb,
                                                      float* __restrict__ out) {
    __shared__ float SB[64 * 36 * 2 + 128 * 36 * 2];  // 55296 B
    float (*Csh)[36] = (float(*)[36])SB;                         // ctx hi
    float (*Csl)[36] = (float(*)[36])(SB + 64 * 36);             // ctx lo
    float (*Whh)[36] = (float(*)[36])(SB + 64 * 36 * 2);         // W hi
    float (*Whl)[36] = (float(*)[36])(SB + 64 * 36 * 2 + 128 * 36);  // W lo
    float (*Osh)[PO] = (float(*)[PO])SB;                         // overlay, 64x133
    __shared__ float mu_s[64], rs_s[64];

    const int b = blockIdx.y;
    const int n0 = blockIdx.x * 64;
    const int t = threadIdx.x;
    const int wid = t >> 5;
    const int lane = t & 31;
    const int lr = lane >> 2;
    const int lc = lane & 3;
    const int wn = (wid & 1) * 32;   // warp n offset
    const int wo = (wid >> 1) * 64;  // warp o offset

    float c[2][8][4];
#pragma unroll
    for (int mb = 0; mb < 2; mb++)
#pragma unroll
        for (int nc = 0; nc < 8; nc++)
#pragma unroll
            for (int i = 0; i < 4; i++) c[mb][nc][i] = 0.f;

    const float* ctx = g_ctx + ((size_t)b * NN + n0) * CC;

    for (int c0 = 0; c0 < CC; c0 += 32) {
        // stage ctx 64n x 32c, hi/lo split
#pragma unroll
        for (int i = t; i < 512; i += 128) {
            int row = i >> 3, cq = (i & 7) * 4;
            float4 v = *(const float4*)&ctx[(size_t)row * CC + c0 + cq];
            float4 h = make_float4(tf32r(v.x), tf32r(v.y), tf32r(v.z), tf32r(v.w));
            float4 l = make_float4(tf32r(v.x - h.x), tf32r(v.y - h.y),
                                   tf32r(v.z - h.z), tf32r(v.w - h.w));
            *(float4*)&Csh[row][cq] = h;
            *(float4*)&Csl[row][cq] = l;
        }
        // stage W 128o x 32c hi/lo, [o][c] layout (no transpose)
#pragma unroll
        for (int i = t; i < 1024; i += 128) {
            int row = i >> 3, cq = (i & 7) * 4;
            float4 v = *(const float4*)&wp[(size_t)row * CC + c0 + cq];
            float4 h = make_float4(tf32r(v.x), tf32r(v.y), tf32r(v.z), tf32r(v.w));
            float4 l = make_float4(tf32r(v.x - h.x), tf32r(v.y - h.y),
                                   tf32r(v.z - h.z), tf32r(v.w - h.w));
            *(float4*)&Whh[row][cq] = h;
            *(float4*)&Whl[row][cq] = l;
        }
        __syncthreads();

#pragma unroll
        for (int kc = 0; kc < 4; kc++) {
            unsigned a[2][4], alo[2][4];
#pragma unroll
            for (int mb = 0; mb < 2; mb++) {
                const int r0 = wn + mb * 16;
                a[mb][0] = __float_as_uint(Csh[r0 + lr][kc * 8 + lc]);
                a[mb][1] = __float_as_uint(Csh[r0 + lr + 8][kc * 8 + lc]);
                a[mb][2] = __float_as_uint(Csh[r0 + lr][kc * 8 + lc + 4]);
                a[mb][3] = __float_as_uint(Csh[r0 + lr + 8][kc * 8 + lc + 4]);
                alo[mb][0] = __float_as_uint(Csl[r0 + lr][kc * 8 + lc]);
                alo[mb][1] = __float_as_uint(Csl[r0 + lr + 8][kc * 8 + lc]);
                alo[mb][2] = __float_as_uint(Csl[r0 + lr][kc * 8 + lc + 4]);
                alo[mb][3] = __float_as_uint(Csl[r0 + lr + 8][kc * 8 + lc + 4]);
            }
#pragma unroll
            for (int nc = 0; nc < 8; nc++) {
                const int orow = wo + nc * 8 + lr;
                unsigned bh0 = __float_as_uint(Whh[orow][kc * 8 + lc]);
                unsigned bh1 = __float_as_uint(Whh[orow][kc * 8 + lc + 4]);
                unsigned bl0 = __float_as_uint(Whl[orow][kc * 8 + lc]);
                unsigned bl1 = __float_as_uint(Whl[orow][kc * 8 + lc + 4]);
#pragma unroll
                for (int mb = 0; mb < 2; mb++) {
                    mma8(c[mb][nc][0], c[mb][nc][1], c[mb][nc][2], c[mb][nc][3],
                         a[mb][0], a[mb][1], a[mb][2], a[mb][3], bh0, bh1);
                    mma8(c[mb][nc][0], c[mb][nc][1], c[mb][nc][2], c[mb][nc][3],
                         a[mb][0], a[mb][1], a[mb][2], a[mb][3], bl0, bl1);
                    mma8(c[mb][nc][0], c[mb][nc][1], c[mb][nc][2], c[mb][nc][3],
                         alo[mb][0], alo[mb][1], alo[mb][2], alo[mb][3], bh0, bh1);
                }
            }
        }
        __syncthreads();
    }

    // frags -> Osh[n][o] (+bias)
#pragma unroll
    for (int mb = 0; mb < 2; mb++) {
        const int r0 = wn + mb * 16;
#pragma unroll
        for (int nc = 0; nc < 8; nc++) {
            const int oc = wo + nc * 8 + 2 * lc;
            float b0 = bp[oc], b1 = bp[oc + 1];
            Osh[r0 + lr][oc] = c[mb][nc][0] + b0;
            Osh[r0 + lr][oc + 1] = c[mb][nc][1] + b1;
            Osh[r0 + lr + 8][oc] = c[mb][nc][2] + b0;
            Osh[r0 + lr + 8][oc + 1] = c[mb][nc][3] + b1;
        }
    }
    __syncthreads();

    // LayerNorm stats: warp w handles rows 16w..16w+15
    {
        for (int r = wid * 16; r < wid * 16 + 16; r++) {
            float sv = 0.f, sq = 0.f;
#pragma unroll
            for (int oq = 0; oq < 4; oq++) {
                float v = Osh[r][lane + 32 * oq];
                sv += v; sq += v * v;
            }
#pragma unroll
            for (int off = 16; off; off >>= 1) {
                sv += __shfl_xor_sync(0xFFFFFFFFu, sv, off);
                sq += __shfl_xor_sync(0xFFFFFFFFu, sq, off);
            }
            if (lane == 0) {
                float mu = sv * (1.f / 128.f);
                float var = sq * (1.f / 128.f) - mu * mu;
                mu_s[r] = mu;
                rs_s[r] = rsqrtf(var + LN_EPS);
            }
        }
    }
    __syncthreads();

    // normalize + transpose write: coalesced over n (64-wide rows)
#pragma unroll
    for (int i = 0; i < 64; i++) {
        int e = t + 128 * i;
        int o = e >> 6, nl = e & 63;
        float v = (Osh[nl][o] - mu_s[nl]) * rs_s[nl] * lg[o] + lb[o];
        out[(size_t)(b * CC + o) * NN + n0 + nl] = v;
    }
}

// =====================================================================
extern "C" void kernel_launch(void* const* d_in, const int* in_sizes, int n_in,
                              void* d_out, int out_size) {
    const float* x      = (const float*)d_in[0];
    const float* w_qkv  = (const float*)d_in[1];
    const float* w_proj = (const float*)d_in[2];
    const float* b_proj = (const float*)d_in[3];
    const float* ln_g   = (const float*)d_in[4];
    const float* ln_b   = (const float*)d_in[5];
    float* out = (float*)d_out;

    dim3 g1(NN / 64, 384 / 64, BB);
    qkv_kernel<<<g1, 128>>>(x, w_qkv);

    pool_kernel<<<(BB * CC * AG + 255) / 256, 256>>>(x);

    dim3 g3((NN + 255) / 256, BB * HEADS);
    stage1_kernel<<<g3, 256>>>();

    dim3 g4(NN / 64, BB * HEADS, KSPLIT);
    flash_kernel<<<g4, 64>>>();

    combine_kernel<<<(BB * HEADS * NN + 255) / 256, 256>>>();

    dim3 g5(NN / 64, BB);
    proj_ln_kernel<<<g5, 128>>>(w_proj, b_proj, ln_g, ln_b, out);
}

// round 16
// speedup vs baseline: 1.8175x; 1.1036x over previous
#include <cuda_runtime.h>
#include <cuda_fp16.h>
#include <cstdint>

#define BB 2
#define CC 128
#define HHW 56
#define NN 3136
#define HEADS 4
#define HD 32
#define AG 49
#define SCALE 0.1767766952966369f  // 32^-0.5
#define LN_EPS 1e-5f
#define KSPLIT 7
#define NTILES 49          // NN / 64

#define SP 36  // fp32 smem pad (floats)
#define HP 40  // fp16 smem pad (halves): bank 20*lr+lc -> conflict-free
#define PO 133 // proj LN epilogue pad

// ---------------- scratch (device globals; no allocation allowed) ----------------
__device__ float g_q[BB * HEADS * NN * HD];
__device__ __half2 g_kh2[BB * HEADS * NN * HD / 2];    // K fp16 [bh][key][d-pairs]
__device__ __half2 g_vh2[BB * HEADS * HD * NN / 2];    // V fp16 [bh][d][key-pairs]
__device__ __half2 g_qch2[BB * HEADS * NN * HD / 2];   // q_c fp16, pre-scaled
__device__ float g_agent[BB * HEADS * AG * HD];
__device__ float g_ctx[BB * NN * CC];
// split-K partials (no max needed: logits are tiny, exp(s) directly)
__device__ float g_po[KSPLIT * BB * HEADS * NN * HD];
__device__ float g_pl[KSPLIT * BB * HEADS * NN];

// ---------------- helpers ----------------
__device__ __forceinline__ float tf32r(float x) {
    asm("cvt.rna.tf32.f32 %0, %0;" : "+f"(x));
    return x;
}

__device__ __forceinline__ void mma8(float& c0, float& c1, float& c2, float& c3,
                                     unsigned a0, unsigned a1, unsigned a2, unsigned a3,
                                     unsigned b0, unsigned b1) {
    asm("mma.sync.aligned.m16n8k8.row.col.f32.tf32.tf32.f32 "
        "{%0,%1,%2,%3}, {%4,%5,%6,%7}, {%8,%9}, {%0,%1,%2,%3};"
        : "+f"(c0), "+f"(c1), "+f"(c2), "+f"(c3)
        : "r"(a0), "r"(a1), "r"(a2), "r"(a3), "r"(b0), "r"(b1));
}

__device__ __forceinline__ void mma16h(float& c0, float& c1, float& c2, float& c3,
                                       unsigned a0, unsigned a1, unsigned a2, unsigned a3,
                                       unsigned b0, unsigned b1) {
    asm("mma.sync.aligned.m16n8k16.row.col.f32.f16.f16.f32 "
        "{%0,%1,%2,%3}, {%4,%5,%6,%7}, {%8,%9}, {%0,%1,%2,%3};"
        : "+f"(c0), "+f"(c1), "+f"(c2), "+f"(c3)
        : "r"(a0), "r"(a1), "r"(a2), "r"(a3), "r"(b0), "r"(b1));
}

__device__ __forceinline__ void cp16(unsigned smem_addr, const void* gptr) {
    asm volatile("cp.async.ca.shared.global [%0], [%1], 16;\n"
                 :: "r"(smem_addr), "l"(gptr));
}

__device__ __forceinline__ unsigned packh2(float a, float b) {
    __half2 h = __floats2half2_rn(a, b);
    return *(unsigned*)&h;
}

// =====================================================================
// Kernel 1: QKV 1x1 conv via 3xTF32 tensor-core GEMM.
// K written fp16 [bh][key][d]; V written fp16 TRANSPOSED [bh][d][key].
// =====================================================================
__global__ __launch_bounds__(128) void qkv_kernel(const float* __restrict__ x,
                                                  const float* __restrict__ w) {
    __shared__ float SB[64 * 36 * 2 + 32 * 68 * 2];  // 35840 B
    float (*Whi)[36] = (float(*)[36])SB;
    float (*Wlo)[36] = (float(*)[36])(SB + 64 * 36);
    float (*Xhi)[68] = (float(*)[68])(SB + 64 * 36 * 2);
    float (*Xlo)[68] = (float(*)[68])(SB + 64 * 36 * 2 + 32 * 68);
    float (*Osh)[68] = (float(*)[68])SB;  // overlay (after k-loop)

    const int b = blockIdx.z;
    const int o0 = blockIdx.y * 64;
    const int n0 = blockIdx.x * 64;
    const int t = threadIdx.x;
    const int wid = t >> 5;
    const int lane = t & 31;
    const int lr = lane >> 2;
    const int lc = lane & 3;
    const int wo2 = (wid >> 1) * 32;
    const int wn2 = (wid & 1) * 32;

    float c[2][4][4];
#pragma unroll
    for (int mb = 0; mb < 2; mb++)
#pragma unroll
        for (int nc = 0; nc < 4; nc++)
#pragma unroll
            for (int i = 0; i < 4; i++) c[mb][nc][i] = 0.f;

    const float* xb = x + (size_t)b * CC * NN;

    for (int k0 = 0; k0 < CC; k0 += 32) {
        {
            int wrow = t >> 3, wcol = (t & 7) * 4;
#pragma unroll
            for (int u = 0; u < 4; u++) {
                int wo = wrow + u * 16;
                float4 v = *(const float4*)&w[(size_t)(o0 + wo) * CC + k0 + wcol];
                float4 h = make_float4(tf32r(v.x), tf32r(v.y), tf32r(v.z), tf32r(v.w));
                float4 l = make_float4(tf32r(v.x - h.x), tf32r(v.y - h.y),
                                       tf32r(v.z - h.z), tf32r(v.w - h.w));
                *(float4*)&Whi[wo][wcol] = h;
                *(float4*)&Wlo[wo][wcol] = l;
            }
        }
        {
            int xrow = t >> 4, xcol = (t & 15) * 4;
#pragma unroll
            for (int u = 0; u < 4; u++) {
                int xc = xrow + u * 8;
                float4 v = *(const float4*)&xb[(size_t)(k0 + xc) * NN + n0 + xcol];
                float4 h = make_float4(tf32r(v.x), tf32r(v.y), tf32r(v.z), tf32r(v.w));
                float4 l = make_float4(tf32r(v.x - h.x), tf32r(v.y - h.y),
                                       tf32r(v.z - h.z), tf32r(v.w - h.w));
                *(float4*)&Xhi[xc][xcol] = h;
                *(float4*)&Xlo[xc][xcol] = l;
            }
        }
        __syncthreads();

#pragma unroll
        for (int kc = 0; kc < 4; kc++) {
            unsigned ah[2][4], al[2][4];
#pragma unroll
            for (int mb = 0; mb < 2; mb++) {
                const int r0 = wo2 + mb * 16;
                ah[mb][0] = __float_as_uint(Whi[r0 + lr][kc * 8 + lc]);
                ah[mb][1] = __float_as_uint(Whi[r0 + lr + 8][kc * 8 + lc]);
                ah[mb][2] = __float_as_uint(Whi[r0 + lr][kc * 8 + lc + 4]);
                ah[mb][3] = __float_as_uint(Whi[r0 + lr + 8][kc * 8 + lc + 4]);
                al[mb][0] = __float_as_uint(Wlo[r0 + lr][kc * 8 + lc]);
                al[mb][1] = __float_as_uint(Wlo[r0 + lr + 8][kc * 8 + lc]);
                al[mb][2] = __float_as_uint(Wlo[r0 + lr][kc * 8 + lc + 4]);
                al[mb][3] = __float_as_uint(Wlo[r0 + lr + 8][kc * 8 + lc + 4]);
            }
#pragma unroll
            for (int nc = 0; nc < 4; nc++) {
                unsigned bh0 = __float_as_uint(Xhi[kc * 8 + lc][wn2 + nc * 8 + lr]);
                unsigned bh1 = __float_as_uint(Xhi[kc * 8 + lc + 4][wn2 + nc * 8 + lr]);
                unsigned bl0 = __float_as_uint(Xlo[kc * 8 + lc][wn2 + nc * 8 + lr]);
                unsigned bl1 = __float_as_uint(Xlo[kc * 8 + lc + 4][wn2 + nc * 8 + lr]);
#pragma unroll
                for (int mb = 0; mb < 2; mb++) {
                    mma8(c[mb][nc][0], c[mb][nc][1], c[mb][nc][2], c[mb][nc][3],
                         ah[mb][0], ah[mb][1], ah[mb][2], ah[mb][3], bh0, bh1);
                    mma8(c[mb][nc][0], c[mb][nc][1], c[mb][nc][2], c[mb][nc][3],
                         ah[mb][0], ah[mb][1], ah[mb][2], ah[mb][3], bl0, bl1);
                    mma8(c[mb][nc][0], c[mb][nc][1], c[mb][nc][2], c[mb][nc][3],
                         al[mb][0], al[mb][1], al[mb][2], al[mb][3], bh0, bh1);
                }
            }
        }
        __syncthreads();
    }

#pragma unroll
    for (int mb = 0; mb < 2; mb++) {
        const int r0 = wo2 + mb * 16;
#pragma unroll
        for (int nc = 0; nc < 4; nc++) {
            *(float2*)&Osh[r0 + lr][wn2 + nc * 8 + 2 * lc] =
                make_float2(c[mb][nc][0], c[mb][nc][1]);
            *(float2*)&Osh[r0 + lr + 8][wn2 + nc * 8 + 2 * lc] =
                make_float2(c[mb][nc][2], c[mb][nc][3]);
        }
    }
    __syncthreads();

    const int part_blk = o0 >> 7;  // 0=q 1=k 2=v
    if (part_blk == 2) {
        // V: fp16 transposed writeout [bh][d][key], half2 pairs along key
#pragma unroll
        for (int i = 0; i < 16; i++) {
            int idx = t + 128 * i;       // 0..2047
            int row = idx >> 5;          // o row 0..63
            int pr = idx & 31;           // key pair 0..31
            int og = o0 + row;
            int head = (og >> 5) & 3;
            int d = og & 31;
            float2 v2 = *(float2*)&Osh[row][2 * pr];
            g_vh2[((size_t)(b * HEADS + head) * HD + d) * (NN / 2) + (n0 >> 1) + pr] =
                __floats2half2_rn(v2.x, v2.y);
        }
    } else if (part_blk == 1) {
        // K: fp16 [bh][key][d-pairs]
#pragma unroll
        for (int i = 0; i < 16; i++) {
            int idx = t + 128 * i;       // 0..2047
            int n = idx >> 5;            // key 0..63
            int dp = idx & 31;           // d-pair across 2 heads
            int hh = dp >> 4, dpl = dp & 15;
            int head = ((o0 >> 5) & 3) + hh;
            unsigned val = packh2(Osh[hh * 32 + 2 * dpl][n], Osh[hh * 32 + 2 * dpl + 1][n]);
            g_kh2[((size_t)(b * HEADS + head) * NN + n0 + n) * 16 + dpl] = *(__half2*)&val;
        }
    } else {
#pragma unroll
        for (int p = 0; p < 8; p++) {
            const int oh = p & 1;
            const int ng = p >> 1;
            const int nrow = ng * 16 + (t >> 3);
            const int dpos = (t & 7) * 4;
            const int og = o0 + oh * 32;
            const int head = (og >> 5) & 3;
            float4 v;
            v.x = Osh[oh * 32 + dpos + 0][nrow];
            v.y = Osh[oh * 32 + dpos + 1][nrow];
            v.z = Osh[oh * 32 + dpos + 2][nrow];
            v.w = Osh[oh * 32 + dpos + 3][nrow];
            *(float4*)&g_q[((size_t)(b * HEADS + head) * NN + n0 + nrow) * HD + dpos] = v;
        }
    }
}

// =====================================================================
// Kernel 2: agent pooling — exact 8x8 block mean
// =====================================================================
__global__ void pool_kernel(const float* __restrict__ x) {
    int idx = blockIdx.x * 256 + threadIdx.x;
    if (idx >= BB * CC * AG) return;
    int a = idx % AG;
    int c = (idx / AG) % CC;
    int b = idx / (AG * CC);
    int ai = a / 7, aj = a % 7;
    const float* p = x + ((size_t)(b * CC + c) * HHW + ai * 8) * HHW + aj * 8;
    float s = 0.f;
#pragma unroll
    for (int r = 0; r < 8; r++) {
        float4 u = *(const float4*)&p[r * HHW];
        float4 u2 = *(const float4*)&p[r * HHW + 4];
        s += u.x + u.y + u.z + u.w + u2.x + u2.y + u2.z + u2.w;
    }
    s *= (1.0f / 64.0f);
    g_agent[((size_t)(b * HEADS + c / HD) * AG + a) * HD + (c % HD)] = s;
}

// =====================================================================
// Kernel 3: stage 1 — softmax over 49 agent tokens; q_c written fp16
// (same mantissa as tf32), pre-scaled by SCALE.
// =====================================================================
__global__ __launch_bounds__(256) void stage1_kernel() {
    __shared__ float Ash[AG][HD];
    const int bh = blockIdx.y;
    const int n = blockIdx.x * 256 + threadIdx.x;

    {
        const float4* src = (const float4*)(g_agent + (size_t)bh * AG * HD);
        float4* dstp = (float4*)&Ash[0][0];
        for (int i = threadIdx.x; i < AG * HD / 4; i += 256) dstp[i] = src[i];
    }
    __syncthreads();
    if (n >= NN) return;

    float4 q[8];
    const float4* qp = (const float4*)(g_q + ((size_t)bh * NN + n) * HD);
#pragma unroll
    for (int i = 0; i < 8; i++) q[i] = qp[i];

    float l = 0.f;
    float4 qc[8];
#pragma unroll
    for (int i = 0; i < 8; i++) qc[i] = make_float4(0.f, 0.f, 0.f, 0.f);

#pragma unroll 7
    for (int a = 0; a < AG; a++) {
        const float4* ar = (const float4*)&Ash[a][0];
        float s = 0.f;
#pragma unroll
        for (int i = 0; i < 8; i++) {
            float4 av = ar[i];
            s += q[i].x * av.x + q[i].y * av.y + q[i].z * av.z + q[i].w * av.w;
        }
        float p = __expf(s * SCALE);  // logits tiny; no max needed
        l += p;
#pragma unroll
        for (int i = 0; i < 8; i++) {
            float4 av = ar[i];
            qc[i].x += p * av.x; qc[i].y += p * av.y;
            qc[i].z += p * av.z; qc[i].w += p * av.w;
        }
    }
    float inv = SCALE / l;
    __half2* op = g_qch2 + ((size_t)bh * NN + n) * 16;
#pragma unroll
    for (int i = 0; i < 8; i++) {
        float4 v = qc[i];
        op[2 * i] = __floats2half2_rn(v.x * inv, v.y * inv);
        op[2 * i + 1] = __floats2half2_rn(v.z * inv, v.w * inv);
    }
}

// =====================================================================
// Kernel 4: stage 2 — all-fp16 tensor-core flash attention.
// S via mma.m16n8k16 (Q,K fp16 == tf32 mantissa -> no extra error),
// P stays in registers (FA2 pack), PV via fp16 mma (V as [d][key]).
// No P smem, no inner syncs. smem ~14.5KB.
// =====================================================================
__global__ __launch_bounds__(64, 8) void flash_kernel() {
    __shared__ __align__(16) __half Qsh[64][HP];
    __shared__ __align__(16) __half Ksh[64][HP];
    __shared__ __align__(16) __half2 Vsh[32][36];  // [d][key-pair]

    const int bh = blockIdx.y;
    const int z = blockIdx.z;
    const int t = threadIdx.x;
    const int w = t >> 5;
    const int lane = t & 31;
    const int lr = lane >> 2;
    const int lc = lane & 3;
    const int nq0 = blockIdx.x * 64;

    const unsigned qsh0 = (unsigned)__cvta_generic_to_shared(&Qsh[0][0]);
    const unsigned ksh0 = (unsigned)__cvta_generic_to_shared(&Ksh[0][0]);
    const unsigned vsh0 = (unsigned)__cvta_generic_to_shared(&Vsh[0][0]);

    // stage Q tile (64 keys x 32 d fp16 = 4KB) via cp.async
    {
        const __half2* qsrc = g_qch2 + ((size_t)bh * NN + nq0) * 16;
#pragma unroll
        for (int i = t; i < 256; i += 64) {
            int r = i >> 2, ch = i & 3;
            cp16(qsh0 + r * (HP * 2) + ch * 16, qsrc + r * 16 + ch * 4);
        }
        asm volatile("cp.async.commit_group;\n");
        asm volatile("cp.async.wait_group 0;\n" ::: "memory");
    }
    __syncthreads();

    // Q A-fragments (fp16 k16): [mb][kc][reg]
    unsigned qa[2][2][4];
#pragma unroll
    for (int mb = 0; mb < 2; mb++) {
        const int r0 = w * 32 + mb * 16;
#pragma unroll
        for (int kc = 0; kc < 2; kc++) {
            qa[mb][kc][0] = *(const unsigned*)&Qsh[r0 + lr][kc * 16 + 2 * lc];
            qa[mb][kc][1] = *(const unsigned*)&Qsh[r0 + lr + 8][kc * 16 + 2 * lc];
            qa[mb][kc][2] = *(const unsigned*)&Qsh[r0 + lr][kc * 16 + 2 * lc + 8];
            qa[mb][kc][3] = *(const unsigned*)&Qsh[r0 + lr + 8][kc * 16 + 2 * lc + 8];
        }
    }

    float o[2][4][4];
#pragma unroll
    for (int mb = 0; mb < 2; mb++)
#pragma unroll
        for (int dc = 0; dc < 4; dc++)
#pragma unroll
            for (int i = 0; i < 4; i++) o[mb][dc][i] = 0.f;
    float la[2] = {0.f, 0.f}, lb[2] = {0.f, 0.f};

    const __half2* kbase = g_kh2 + (size_t)bh * NN * 16;
    const __half2* vbase = g_vh2 + (size_t)bh * HD * (NN / 2);

    const int tstart = (NTILES * z) / KSPLIT;
    const int tend = (NTILES * (z + 1)) / KSPLIT;

    for (int tt = tstart; tt < tend; tt++) {
        // stage K (64key x 32d fp16) + V (32d x 64key fp16) via cp.async
        {
            const __half2* ks = kbase + (size_t)tt * 64 * 16;
#pragma unroll
            for (int i = t; i < 256; i += 64) {
                int r = i >> 2, ch = i & 3;
                cp16(ksh0 + r * (HP * 2) + ch * 16, ks + r * 16 + ch * 4);
            }
#pragma unroll
            for (int i = t; i < 256; i += 64) {
                int d = i >> 3, ch = i & 7;
                cp16(vsh0 + d * 144 + ch * 16,
                     vbase + (size_t)d * (NN / 2) + tt * 32 + ch * 4);
            }
            asm volatile("cp.async.commit_group;\n");
            asm volatile("cp.async.wait_group 0;\n" ::: "memory");
        }
        __syncthreads();

        // 16-key groups: S (fp16 mma) -> exp -> reg-pack -> PV (fp16 mma)
#pragma unroll
        for (int g = 0; g < 4; g++) {
            float s[2][2][4];  // [blk][mb][reg]
#pragma unroll
            for (int blk = 0; blk < 2; blk++) {
                const int krow = (2 * g + blk) * 8 + lr;
#pragma unroll
                for (int mb = 0; mb < 2; mb++)
#pragma unroll
                    for (int i = 0; i < 4; i++) s[blk][mb][i] = 0.f;
                unsigned b00 = *(const unsigned*)&Ksh[krow][2 * lc];
                unsigned b01 = *(const unsigned*)&Ksh[krow][2 * lc + 8];
                mma16h(s[blk][0][0], s[blk][0][1], s[blk][0][2], s[blk][0][3],
                       qa[0][0][0], qa[0][0][1], qa[0][0][2], qa[0][0][3], b00, b01);
                mma16h(s[blk][1][0], s[blk][1][1], s[blk][1][2], s[blk][1][3],
                       qa[1][0][0], qa[1][0][1], qa[1][0][2], qa[1][0][3], b00, b01);
                unsigned b10 = *(const unsigned*)&Ksh[krow][16 + 2 * lc];
                unsigned b11 = *(const unsigned*)&Ksh[krow][16 + 2 * lc + 8];
                mma16h(s[blk][0][0], s[blk][0][1], s[blk][0][2], s[blk][0][3],
                       qa[0][1][0], qa[0][1][1], qa[0][1][2], qa[0][1][3], b10, b11);
                mma16h(s[blk][1][0], s[blk][1][1], s[blk][1][2], s[blk][1][3],
                       qa[1][1][0], qa[1][1][1], qa[1][1][2], qa[1][1][3], b10, b11);
            }
            unsigned pa[2][4];
#pragma unroll
            for (int mb = 0; mb < 2; mb++) {
                float p00 = __expf(s[0][mb][0]);
                float p01 = __expf(s[0][mb][1]);
                float p02 = __expf(s[0][mb][2]);
                float p03 = __expf(s[0][mb][3]);
                float p10 = __expf(s[1][mb][0]);
                float p11 = __expf(s[1][mb][1]);
                float p12 = __expf(s[1][mb][2]);
                float p13 = __expf(s[1][mb][3]);
                la[mb] += p00 + p01 + p10 + p11;  // row mb*16+lr
                lb[mb] += p02 + p03 + p12 + p13;  // row mb*16+lr+8
                pa[mb][0] = packh2(p00, p01);
                pa[mb][1] = packh2(p02, p03);
                pa[mb][2] = packh2(p10, p11);
                pa[mb][3] = packh2(p12, p13);
            }
#pragma unroll
            for (int dc = 0; dc < 4; dc++) {
                unsigned b0 = *(const unsigned*)&Vsh[dc * 8 + lr][8 * g + lc];
                unsigned b1 = *(const unsigned*)&Vsh[dc * 8 + lr][8 * g + lc + 4];
                mma16h(o[0][dc][0], o[0][dc][1], o[0][dc][2], o[0][dc][3],
                       pa[0][0], pa[0][1], pa[0][2], pa[0][3], b0, b1);
                mma16h(o[1][dc][0], o[1][dc][1], o[1][dc][2], o[1][dc][3],
                       pa[1][0], pa[1][1], pa[1][2], pa[1][3], b0, b1);
            }
        }
        __syncthreads();  // K/V reads done before next tile staging
    }

    // epilogue: reduce l over the quad owning each row, write partials
#pragma unroll
    for (int mb = 0; mb < 2; mb++) {
        la[mb] += __shfl_xor_sync(0xFFFFFFFFu, la[mb], 1);
        la[mb] += __shfl_xor_sync(0xFFFFFFFFu, la[mb], 2);
        lb[mb] += __shfl_xor_sync(0xFFFFFFFFu, lb[mb], 1);
        lb[mb] += __shfl_xor_sync(0xFFFFFFFFu, lb[mb], 2);
    }

    const size_t prow = ((size_t)z * BB * HEADS + bh) * NN + nq0 + w * 32;
#pragma unroll
    for (int mb = 0; mb < 2; mb++) {
        const size_t r0 = prow + mb * 16;
        if (lc == 0) {
            g_pl[r0 + lr] = la[mb];
            g_pl[r0 + lr + 8] = lb[mb];
        }
#pragma unroll
        for (int dc = 0; dc < 4; dc++) {
            *(float2*)&g_po[(r0 + lr) * HD + dc * 8 + 2 * lc] =
                make_float2(o[mb][dc][0], o[mb][dc][1]);
            *(float2*)&g_po[(r0 + lr + 8) * HD + dc * 8 + 2 * lc] =
                make_float2(o[mb][dc][2], o[mb][dc][3]);
        }
    }
}

// =====================================================================
// Kernel 4b: combine split-K partials -> ctx [b, n, c]
// =====================================================================
__global__ __launch_bounds__(256) void combine_kernel() {
    const int idx = blockIdx.x * 256 + threadIdx.x;  // over bh*NN
    if (idx >= BB * HEADS * NN) return;
    const int bh = idx / NN;
    const int n = idx % NN;

    float L = 0.f;
    float4 acc[8];
#pragma unroll
    for (int i = 0; i < 8; i++) acc[i] = make_float4(0.f, 0.f, 0.f, 0.f);
#pragma unroll
    for (int z = 0; z < KSPLIT; z++) {
        const size_t pidx = ((size_t)z * BB * HEADS + bh) * NN + n;
        L += g_pl[pidx];
        const float4* op = (const float4*)(g_po + pidx * HD);
#pragma unroll
        for (int i = 0; i < 8; i++) {
            float4 v = op[i];
            acc[i].x += v.x; acc[i].y += v.y;
            acc[i].z += v.z; acc[i].w += v.w;
        }
    }
    float inv = 1.f / L;
    const int b = bh / HEADS, h = bh % HEADS;
    float4* dst = (float4*)(g_ctx + ((size_t)b * NN + n) * CC + h * HD);
#pragma unroll
    for (int i = 0; i < 8; i++) {
        float4 v = acc[i];
        dst[i] = make_float4(v.x * inv, v.y * inv, v.z * inv, v.w * inv);
    }
}

// =====================================================================
// Kernel 5: proj GEMM via 3-term tf32 mma (Ch*Wh + Ch*Wl + Cl*Wh)
// + bias + LayerNorm + transpose to [b,c,n].
// =====================================================================
__global__ __launch_bounds__(128) void proj_ln_kernel(const float* __restrict__ wp,
                                                      const float* __restrict__ bp,
                                                      const float* __restrict__ lg,
                                                      const float* __restrict__ lb,
                                                      float* __restrict__ out) {
    __shared__ float SB[64 * 36 * 2 + 128 * 36 * 2];  // 55296 B
    float (*Csh)[36] = (float(*)[36])SB;                         // ctx hi
    float (*Csl)[36] = (float(*)[36])(SB + 64 * 36);             // ctx lo
    float (*Whh)[36] = (float(*)[36])(SB + 64 * 36 * 2);         // W hi
    float (*Whl)[36] = (float(*)[36])(SB + 64 * 36 * 2 + 128 * 36);  // W lo
    float (*Osh)[PO] = (float(*)[PO])SB;                         // overlay, 64x133
    __shared__ float mu_s[64], rs_s[64];

    const int b = blockIdx.y;
    const int n0 = blockIdx.x * 64;
    const int t = threadIdx.x;
    const int wid = t >> 5;
    const int lane = t & 31;
    const int lr = lane >> 2;
    const int lc = lane & 3;
    const int wn = (wid & 1) * 32;   // warp n offset
    const int wo = (wid >> 1) * 64;  // warp o offset

    float c[2][8][4];
#pragma unroll
    for (int mb = 0; mb < 2; mb++)
#pragma unroll
        for (int nc = 0; nc < 8; nc++)
#pragma unroll
            for (int i = 0; i < 4; i++) c[mb][nc][i] = 0.f;

    const float* ctx = g_ctx + ((size_t)b * NN + n0) * CC;

    for (int c0 = 0; c0 < CC; c0 += 32) {
#pragma unroll
        for (int i = t; i < 512; i += 128) {
            int row = i >> 3, cq = (i & 7) * 4;
            float4 v = *(const float4*)&ctx[(size_t)row * CC + c0 + cq];
            float4 h = make_float4(tf32r(v.x), tf32r(v.y), tf32r(v.z), tf32r(v.w));
            float4 l = make_float4(tf32r(v.x - h.x), tf32r(v.y - h.y),
                                   tf32r(v.z - h.z), tf32r(v.w - h.w));
            *(float4*)&Csh[row][cq] = h;
            *(float4*)&Csl[row][cq] = l;
        }
#pragma unroll
        for (int i = t; i < 1024; i += 128) {
            int row = i >> 3, cq = (i & 7) * 4;
            float4 v = *(const float4*)&wp[(size_t)row * CC + c0 + cq];
            float4 h = make_float4(tf32r(v.x), tf32r(v.y), tf32r(v.z), tf32r(v.w));
            float4 l = make_float4(tf32r(v.x - h.x), tf32r(v.y - h.y),
                                   tf32r(v.z - h.z), tf32r(v.w - h.w));
            *(float4*)&Whh[row][cq] = h;
            *(float4*)&Whl[row][cq] = l;
        }
        __syncthreads();

#pragma unroll
        for (int kc = 0; kc < 4; kc++) {
            unsigned a[2][4], alo[2][4];
#pragma unroll
            for (int mb = 0; mb < 2; mb++) {
                const int r0 = wn + mb * 16;
                a[mb][0] = __float_as_uint(Csh[r0 + lr][kc * 8 + lc]);
                a[mb][1] = __float_as_uint(Csh[r0 + lr + 8][kc * 8 + lc]);
                a[mb][2] = __float_as_uint(Csh[r0 + lr][kc * 8 + lc + 4]);
                a[mb][3] = __float_as_uint(Csh[r0 + lr + 8][kc * 8 + lc + 4]);
                alo[mb][0] = __float_as_uint(Csl[r0 + lr][kc * 8 + lc]);
                alo[mb][1] = __float_as_uint(Csl[r0 + lr + 8][kc * 8 + lc]);
                alo[mb][2] = __float_as_uint(Csl[r0 + lr][kc * 8 + lc + 4]);
                alo[mb][3] = __float_as_uint(Csl[r0 + lr + 8][kc * 8 + lc + 4]);
            }
#pragma unroll
            for (int nc = 0; nc < 8; nc++) {
                const int orow = wo + nc * 8 + lr;
                unsigned bh0 = __float_as_uint(Whh[orow][kc * 8 + lc]);
                unsigned bh1 = __float_as_uint(Whh[orow][kc * 8 + lc + 4]);
                unsigned bl0 = __float_as_uint(Whl[orow][kc * 8 + lc]);
                unsigned bl1 = __float_as_uint(Whl[orow][kc * 8 + lc + 4]);
#pragma unroll
                for (int mb = 0; mb < 2; mb++) {
                    mma8(c[mb][nc][0], c[mb][nc][1], c[mb][nc][2], c[mb][nc][3],
                         a[mb][0], a[mb][1], a[mb][2], a[mb][3], bh0, bh1);
                    mma8(c[mb][nc][0], c[mb][nc][1], c[mb][nc][2], c[mb][nc][3],
                         a[mb][0], a[mb][1], a[mb][2], a[mb][3], bl0, bl1);
                    mma8(c[mb][nc][0], c[mb][nc][1], c[mb][nc][2], c[mb][nc][3],
                         alo[mb][0], alo[mb][1], alo[mb][2], alo[mb][3], bh0, bh1);
                }
            }
        }
        __syncthreads();
    }

#pragma unroll
    for (int mb = 0; mb < 2; mb++) {
        const int r0 = wn + mb * 16;
#pragma unroll
        for (int nc = 0; nc < 8; nc++) {
            const int oc = wo + nc * 8 + 2 * lc;
            float b0 = bp[oc], b1 = bp[oc + 1];
            Osh[r0 + lr][oc] = c[mb][nc][0] + b0;
            Osh[r0 + lr][oc + 1] = c[mb][nc][1] + b1;
            Osh[r0 + lr + 8][oc] = c[mb][nc][2] + b0;
            Osh[r0 + lr + 8][oc + 1] = c[mb][nc][3] + b1;
        }
    }
    __syncthreads();

    {
        for (int r = wid * 16; r < wid * 16 + 16; r++) {
            float sv = 0.f, sq = 0.f;
#pragma unroll
            for (int oq = 0; oq < 4; oq++) {
                float v = Osh[r][lane + 32 * oq];
                sv += v; sq += v * v;
            }
#pragma unroll
            for (int off = 16; off; off >>= 1) {
                sv += __shfl_xor_sync(0xFFFFFFFFu, sv, off);
                sq += __shfl_xor_sync(0xFFFFFFFFu, sq, off);
            }
            if (lane == 0) {
                float mu = sv * (1.f / 128.f);
                float var = sq * (1.f / 128.f) - mu * mu;
                mu_s[r] = mu;
                rs_s[r] = rsqrtf(var + LN_EPS);
            }
        }
    }
    __syncthreads();

#pragma unroll
    for (int i = 0; i < 64; i++) {
        int e = t + 128 * i;
        int o = e >> 6, nl = e & 63;
        float v = (Osh[nl][o] - mu_s[nl]) * rs_s[nl] * lg[o] + lb[o];
        out[(size_t)(b * CC + o) * NN + n0 + nl] = v;
    }
}

// =====================================================================
extern "C" void kernel_launch(void* const* d_in, const int* in_sizes, int n_in,
                              void* d_out, int out_size) {
    const float* x      = (const float*)d_in[0];
    const float* w_qkv  = (const float*)d_in[1];
    const float* w_proj = (const float*)d_in[2];
    const float* b_proj = (const float*)d_in[3];
    const float* ln_g   = (const float*)d_in[4];
    const float* ln_b   = (const float*)d_in[5];
    float* out = (float*)d_out;

    dim3 g1(NN / 64, 384 / 64, BB);
    qkv_kernel<<<g1, 128>>>(x, w_qkv);

    pool_kernel<<<(BB * CC * AG + 255) / 256, 256>>>(x);

    dim3 g3((NN + 255) / 256, BB * HEADS);
    stage1_kernel<<<g3, 256>>>();

    dim3 g4(NN / 64, BB * HEADS, KSPLIT);
    flash_kernel<<<g4, 64>>>();

    combine_kernel<<<(BB * HEADS * NN + 255) / 256, 256>>>();

    dim3 g5(NN / 64, BB);
    proj_ln_kernel<<<g5, 128>>>(w_proj, b_proj, ln_g, ln_b, out);
}